// round 8
// baseline (speedup 1.0000x reference)
#include <cuda_runtime.h>
#include <cuda_bf16.h>
#include <cstdint>

// Problem sizes
#define BSZ   256
#define TLEN  1024
#define INDIM 302
#define HDIM  512
#define GDIM  1536           // 3*H
#define BT    (BSZ*TLEN)     // 262144

// ---------------- device scratch (static; no cudaMalloc) -------------------
static __device__ float    d_IG[(size_t)TLEN * BSZ * GDIM];   // [T][B][3H] fp32
static __device__ float    d_h[2][BSZ * HDIM];                // fp32 hidden, double buffer
static __device__ unsigned d_bar;                             // scan generation barrier

// ---------------- accurate, fast-math-immune transcendentals ---------------
__device__ __forceinline__ float my_exp(float x) {
    x = fminf(fmaxf(x, -87.0f), 87.0f);
    float n = rintf(x * 1.44269504088896341f);
    float r = fmaf(n, -0.693145751953125f, x);      // ln2_hi
    r = fmaf(n, -1.4286067653e-6f, r);              // ln2_lo
    float p = 1.9841269841e-4f;                     // 1/5040
    p = fmaf(p, r, 1.3888888889e-3f);               // 1/720
    p = fmaf(p, r, 8.3333333333e-3f);               // 1/120
    p = fmaf(p, r, 4.1666666667e-2f);               // 1/24
    p = fmaf(p, r, 1.6666666667e-1f);               // 1/6
    p = fmaf(p, r, 5.0e-1f);
    p = fmaf(p, r, 1.0f);
    p = fmaf(p, r, 1.0f);                           // = 1 + r + ... + r^7/5040
    float s = __int_as_float(((int)n + 127) << 23);
    return p * s;
}
__device__ __forceinline__ float my_sig(float x) {
    return __fdiv_rn(1.0f, 1.0f + my_exp(-x));
}
__device__ __forceinline__ float my_tanh(float x) {
    float s = fabsf(x);
    float q = my_exp(-2.0f * s);
    float t = __fdiv_rn(1.0f - q, 1.0f + q);
    return copysignf(t, x);
}

// ---------------- threefry2x32 with key (0, 42) ----------------------------
__device__ __forceinline__ uint2 threefry_0_42(uint32_t x0, uint32_t x1) {
    const uint32_t k0 = 0u, k1 = 42u;
    const uint32_t k2 = k0 ^ k1 ^ 0x1BD11BDAu;
    const uint32_t ks[3] = {k0, k1, k2};
    const int rotA[4] = {13, 15, 26, 6};
    const int rotB[4] = {17, 29, 16, 24};
    x0 += ks[0]; x1 += ks[1];
#pragma unroll
    for (int i = 0; i < 5; i++) {
        const int* r = (i & 1) ? rotB : rotA;
#pragma unroll
        for (int j = 0; j < 4; j++) {
            x0 += x1;
            x1 = (x1 << r[j]) | (x1 >> (32 - r[j]));
            x1 ^= x0;
        }
        x0 += ks[(i + 1) % 3];
        x1 += ks[(i + 2) % 3] + (uint32_t)(i + 1);
    }
    return make_uint2(x0, x1);
}

// ---------------- init: zero h0, reset barrier ------------------------------
__global__ void init_kernel() {
    int idx = blockIdx.x * blockDim.x + threadIdx.x;
    if (idx == 0) d_bar = 0u;
    int n = BSZ * HDIM;
    for (int i = idx; i < n; i += gridDim.x * blockDim.x) d_h[0][i] = 0.f;
}

// ---------------- IG GEMM (pure fp32 SIMT): IG = X @ W_ih^T + b ------------
__global__ void __launch_bounds__(256) ig_gemm(const float* __restrict__ x,
                                               const float* __restrict__ w_ih,
                                               const float* __restrict__ bias) {
    __shared__ float As[64][17];
    __shared__ float Bs[64][17];
    const int tid = threadIdx.x;
    const int tx = tid & 15, ty = tid >> 4;
    const int g0 = blockIdx.x * 64;
    const int m0 = blockIdx.y * 64;

    float acc[4][4];
#pragma unroll
    for (int i = 0; i < 4; i++)
#pragma unroll
        for (int j = 0; j < 4; j++) acc[i][j] = 0.f;

    for (int kt = 0; kt < 19; kt++) {        // 19*16 = 304 >= 302
        int kb = kt * 16;
        for (int idx = tid; idx < 1024; idx += 256) {
            int row = idx >> 4, k = idx & 15;
            int kg = kb + k;
            As[row][k] = (kg < INDIM) ? x[(size_t)(m0 + row) * INDIM + kg] : 0.f;
            Bs[row][k] = (kg < INDIM) ? w_ih[(size_t)(g0 + row) * INDIM + kg] : 0.f;
        }
        __syncthreads();
#pragma unroll
        for (int kk = 0; kk < 16; kk++) {
            float a[4], bv[4];
#pragma unroll
            for (int i = 0; i < 4; i++) a[i] = As[ty * 4 + i][kk];
#pragma unroll
            for (int j = 0; j < 4; j++) bv[j] = Bs[tx * 4 + j][kk];
#pragma unroll
            for (int i = 0; i < 4; i++)
#pragma unroll
                for (int j = 0; j < 4; j++) acc[i][j] = fmaf(a[i], bv[j], acc[i][j]);
        }
        __syncthreads();
    }

    // scatter: m = b*1024 + t  ->  IG[t][b][g]
#pragma unroll
    for (int i = 0; i < 4; i++) {
        int m = m0 + ty * 4 + i;
        int tt = m & 1023, bb = m >> 10;
#pragma unroll
        for (int j = 0; j < 4; j++) {
            int g = g0 + tx * 4 + j;
            d_IG[((size_t)tt * BSZ + bb) * GDIM + g] = acc[i][j] + bias[g];
        }
    }
}

// ---------------- persistent GRU scan, fp32 SIMT ----------------------------
#define SCAN_CTAS 128
__global__ void __launch_bounds__(256) scan_kernel(const float* __restrict__ w_hh,
                                                   const float* __restrict__ b_n) {
    __shared__ float As[32][33];   // stride 33: odd -> conflict-free
    __shared__ float Bs[96][33];
    const int tid = threadIdx.x;
    const int tx = tid & 31, ty = tid >> 5;
    const int c0 = (blockIdx.x & 15) * 32;
    const int r0 = (blockIdx.x >> 4) * 32;
    const int hc = c0 + tx;

    const float bn = b_n[hc];
    float hreg[4] = {0.f, 0.f, 0.f, 0.f};

    for (int t = 0; t < TLEN; t++) {
        const float* __restrict__ hin = d_h[t & 1];
        float* __restrict__ hout = d_h[(t + 1) & 1];

        float acc[4][3];
#pragma unroll
        for (int i = 0; i < 4; i++)
#pragma unroll
            for (int g = 0; g < 3; g++) acc[i][g] = 0.f;

        for (int kt = 0; kt < 16; kt++) {   // k-tile = 32
            int kb = kt * 32;
            {   // A: 32 rows x 32 k; __ldcg — cross-CTA data, bypass stale L1
                int row = tid >> 3, seg = tid & 7;
                float4 v = __ldcg((const float4*)&hin[(r0 + row) * HDIM + kb + seg * 4]);
                As[row][seg * 4 + 0] = v.x;
                As[row][seg * 4 + 1] = v.y;
                As[row][seg * 4 + 2] = v.z;
                As[row][seg * 4 + 3] = v.w;
            }
#pragma unroll
            for (int i = 0; i < 3; i++) {   // B: 96 rows x 32 k
                int idx = tid + i * 256;
                int row = idx >> 3, seg = idx & 7;
                int gate = row >> 5, hl = row & 31;
                float4 v = *(const float4*)&w_hh[(size_t)((gate << 9) + c0 + hl) * HDIM + kb + seg * 4];
                Bs[row][seg * 4 + 0] = v.x;
                Bs[row][seg * 4 + 1] = v.y;
                Bs[row][seg * 4 + 2] = v.z;
                Bs[row][seg * 4 + 3] = v.w;
            }
            __syncthreads();
#pragma unroll
            for (int kk = 0; kk < 32; kk++) {
                float a0 = As[ty * 4 + 0][kk];
                float a1 = As[ty * 4 + 1][kk];
                float a2 = As[ty * 4 + 2][kk];
                float a3 = As[ty * 4 + 3][kk];
                float b0 = Bs[tx][kk];          // gate r
                float b1 = Bs[32 + tx][kk];     // gate z
                float b2 = Bs[64 + tx][kk];     // gate n
                acc[0][0] = fmaf(a0, b0, acc[0][0]);
                acc[1][0] = fmaf(a1, b0, acc[1][0]);
                acc[2][0] = fmaf(a2, b0, acc[2][0]);
                acc[3][0] = fmaf(a3, b0, acc[3][0]);
                acc[0][1] = fmaf(a0, b1, acc[0][1]);
                acc[1][1] = fmaf(a1, b1, acc[1][1]);
                acc[2][1] = fmaf(a2, b1, acc[2][1]);
                acc[3][1] = fmaf(a3, b1, acc[3][1]);
                acc[0][2] = fmaf(a0, b2, acc[0][2]);
                acc[1][2] = fmaf(a1, b2, acc[1][2]);
                acc[2][2] = fmaf(a2, b2, acc[2][2]);
                acc[3][2] = fmaf(a3, b2, acc[3][2]);
            }
            __syncthreads();
        }

        // epilogue: r = sig(ir+hr), z = sig(iz+hz), n = tanh(in + r*(hn+b_n)),
        // h' = n + z*(h - n); h_old lives in hreg (registers).
#pragma unroll
        for (int i = 0; i < 4; i++) {
            int rb = r0 + ty * 4 + i;
            size_t base = ((size_t)t * BSZ + rb) * GDIM + hc;
            float ir  = d_IG[base];
            float iz  = d_IG[base + 512];
            float inn = d_IG[base + 1024];
            float rg = my_sig(ir + acc[i][0]);
            float zg = my_sig(iz + acc[i][1]);
            float ng = my_tanh(inn + rg * (acc[i][2] + bn));
            float v = ng + zg * (hreg[i] - ng);
            hreg[i] = v;
            hout[rb * HDIM + hc] = v;
        }

        // device-wide generation barrier (monotonic counter)
        if (t < TLEN - 1) {
            __threadfence();                      // release: publish hout
            __syncthreads();
            if (tid == 0) {
                atomicAdd(&d_bar, 1u);
                unsigned tgt = (unsigned)SCAN_CTAS * (unsigned)(t + 1);
                volatile unsigned* p = &d_bar;
                while (*p < tgt) { }
                __threadfence();                  // acquire
            }
            __syncthreads();
        }
    }
}

// ---------------- tail: dropout (threefry, PARTITIONABLE) + LN + MLP -------
// JAX >= 0.4.30 defaults jax_threefry_partitionable=True. 32-bit random bits
// for element with linear index i (row-major over (256,512)):
//   hi = uint32(i >> 32) = 0, lo = uint32(i)
//   (b1, b2) = threefry2x32(key=(0,42), x0=hi, x1=lo)
//   bits = b1 ^ b2
// uniform u = bitcast((bits>>9)|0x3f800000)-1; keep = u < 0.5 <=> bits>>31 == 0.
__global__ void __launch_bounds__(256) tail_kernel(
    const float* __restrict__ ln_w, const float* __restrict__ ln_b,
    const float* __restrict__ w1, const float* __restrict__ b1,
    const float* __restrict__ w2, const float* __restrict__ ob,
    float* __restrict__ out) {
    __shared__ float hs[512];
    __shared__ float r1[256], r2[256];
    const int bidx = blockIdx.x, tid = threadIdx.x;
    const float* __restrict__ hfin = d_h[0];   // final state after t=1023 step

    float s = 0.f, q = 0.f;
    for (int k = tid; k < 512; k += 256) {
        int i = bidx * 512 + k;
        uint2 o = threefry_0_42(0u, (uint32_t)i);   // (hi=0, lo=i)
        uint32_t bits = o.x ^ o.y;                  // partitionable 32-bit draw
        float v = (bits >> 31) ? 0.f : hfin[i] * 2.0f;
        hs[k] = v;
        s += v;
        q += v * v;
    }
    r1[tid] = s; r2[tid] = q;
    __syncthreads();
    for (int off = 128; off > 0; off >>= 1) {
        if (tid < off) { r1[tid] += r1[tid + off]; r2[tid] += r2[tid + off]; }
        __syncthreads();
    }
    float mu = r1[0] * (1.f / 512.f);
    float var = r2[0] * (1.f / 512.f) - mu * mu;
    float rstd = rsqrtf(var + 1e-5f);
    __syncthreads();
    for (int k = tid; k < 512; k += 256)
        hs[k] = (hs[k] - mu) * rstd * ln_w[k] + ln_b[k];
    __syncthreads();

    float a1 = b1[tid];
    const float* wrow = w1 + (size_t)tid * 512;
#pragma unroll 8
    for (int k = 0; k < 512; k++) a1 = fmaf(hs[k], wrow[k], a1);

    float p0 = a1 * w2[tid];
    float p1 = a1 * w2[256 + tid];
    __syncthreads();
    r1[tid] = p0; r2[tid] = p1;
    __syncthreads();
    for (int off = 128; off > 0; off >>= 1) {
        if (tid < off) { r1[tid] += r1[tid + off]; r2[tid] += r2[tid + off]; }
        __syncthreads();
    }
    if (tid == 0) {
        out[bidx * 2 + 0] = my_sig(r1[0] + ob[0]);
        out[bidx * 2 + 1] = my_sig(r2[0] + ob[1]);
    }
}

// ---------------- launcher --------------------------------------------------
extern "C" void kernel_launch(void* const* d_in, const int* in_sizes, int n_in,
                              void* d_out, int out_size) {
    const float* x     = (const float*)d_in[0];
    const float* w_ih  = (const float*)d_in[1];
    const float* w_hh  = (const float*)d_in[2];
    const float* b     = (const float*)d_in[3];
    const float* b_n   = (const float*)d_in[4];
    const float* ln_w  = (const float*)d_in[5];
    const float* ln_b  = (const float*)d_in[6];
    const float* w1    = (const float*)d_in[7];
    const float* b1    = (const float*)d_in[8];
    const float* w2    = (const float*)d_in[9];
    const float* ob    = (const float*)d_in[10];
    float* out = (float*)d_out;

    init_kernel<<<64, 256>>>();
    ig_gemm<<<dim3(GDIM / 64, BT / 64), 256>>>(x, w_ih, b);
    scan_kernel<<<SCAN_CTAS, 256>>>(w_hh, b_n);
    tail_kernel<<<BSZ, 256>>>(ln_w, ln_b, w1, b1, w2, ob, out);
}

// round 12
// speedup vs baseline: 1.4149x; 1.4149x over previous
#include <cuda_runtime.h>
#include <cuda_fp16.h>
#include <cuda_bf16.h>
#include <cstdint>

// Problem sizes
#define BSZ   256
#define TLEN  1024
#define INDIM 302
#define INPAD 304            // padded K (mult of 16)
#define HDIM  512
#define GDIM  1536           // 3*H
#define BT    (BSZ*TLEN)     // 262144

// ---------------- device scratch (static; no cudaMalloc) -------------------
static __device__ __half   d_Xhi[(size_t)BT * INPAD];
static __device__ __half   d_Xlo[(size_t)BT * INPAD];
static __device__ __half   d_Wih_hi[(size_t)GDIM * INPAD];
static __device__ __half   d_Wih_lo[(size_t)GDIM * INPAD];
static __device__ __half   d_Whh_hi[(size_t)GDIM * HDIM];
static __device__ __half   d_Whh_lo[(size_t)GDIM * HDIM];
static __device__ float    d_IG[(size_t)TLEN * BSZ * GDIM];    // [T][B][3H]
static __device__ __half   d_hhi[2][BSZ * HDIM];
static __device__ __half   d_hlo[2][BSZ * HDIM];
static __device__ float    d_hfinal[BSZ * HDIM];
static __device__ unsigned d_bar;

// ---------------- accurate, fast-math-immune transcendentals ---------------
__device__ __forceinline__ float my_exp(float x) {
    x = fminf(fmaxf(x, -87.0f), 87.0f);
    float n = rintf(x * 1.44269504088896341f);
    float r = fmaf(n, -0.693145751953125f, x);      // ln2_hi
    r = fmaf(n, -1.4286067653e-6f, r);              // ln2_lo
    float p = 1.9841269841e-4f;
    p = fmaf(p, r, 1.3888888889e-3f);
    p = fmaf(p, r, 8.3333333333e-3f);
    p = fmaf(p, r, 4.1666666667e-2f);
    p = fmaf(p, r, 1.6666666667e-1f);
    p = fmaf(p, r, 5.0e-1f);
    p = fmaf(p, r, 1.0f);
    p = fmaf(p, r, 1.0f);
    float s = __int_as_float(((int)n + 127) << 23);
    return p * s;
}
__device__ __forceinline__ float my_sig(float x) {
    return __fdiv_rn(1.0f, 1.0f + my_exp(-x));
}
__device__ __forceinline__ float my_tanh(float x) {
    float s = fabsf(x);
    float q = my_exp(-2.0f * s);
    float t = __fdiv_rn(1.0f - q, 1.0f + q);
    return copysignf(t, x);
}

// ---------------- mma.sync m16n8k16 fp16->fp32 -----------------------------
__device__ __forceinline__ void mma16816(float* c, const uint32_t* a, uint32_t b0, uint32_t b1) {
    asm volatile(
        "mma.sync.aligned.m16n8k16.row.col.f32.f16.f16.f32 "
        "{%0,%1,%2,%3}, {%4,%5,%6,%7}, {%8,%9}, {%0,%1,%2,%3};\n"
        : "+f"(c[0]), "+f"(c[1]), "+f"(c[2]), "+f"(c[3])
        : "r"(a[0]), "r"(a[1]), "r"(a[2]), "r"(a[3]), "r"(b0), "r"(b1));
}

// ---------------- threefry2x32 with key (0, 42) ----------------------------
__device__ __forceinline__ uint2 threefry_0_42(uint32_t x0, uint32_t x1) {
    const uint32_t k0 = 0u, k1 = 42u;
    const uint32_t k2 = k0 ^ k1 ^ 0x1BD11BDAu;
    const uint32_t ks[3] = {k0, k1, k2};
    const int rotA[4] = {13, 15, 26, 6};
    const int rotB[4] = {17, 29, 16, 24};
    x0 += ks[0]; x1 += ks[1];
#pragma unroll
    for (int i = 0; i < 5; i++) {
        const int* r = (i & 1) ? rotB : rotA;
#pragma unroll
        for (int j = 0; j < 4; j++) {
            x0 += x1;
            x1 = (x1 << r[j]) | (x1 >> (32 - r[j]));
            x1 ^= x0;
        }
        x0 += ks[(i + 1) % 3];
        x1 += ks[(i + 2) % 3] + (uint32_t)(i + 1);
    }
    return make_uint2(x0, x1);
}

// ---------------- split helpers --------------------------------------------
__device__ __forceinline__ void split16(float v, __half& hi, __half& lo) {
    hi = __float2half(v);
    lo = __float2half(v - __half2float(hi));
}

// ---------------- conversion kernels ---------------------------------------
__global__ void conv_x_kernel(const float* __restrict__ x) {
    int m0 = blockIdx.x * 8;
#pragma unroll
    for (int r = 0; r < 8; r++) {
        int m = m0 + r;
        const float* src = x + (size_t)m * INDIM;
        __half* dh = d_Xhi + (size_t)m * INPAD;
        __half* dl = d_Xlo + (size_t)m * INPAD;
        for (int k = threadIdx.x; k < INPAD; k += blockDim.x) {
            float v = (k < INDIM) ? src[k] : 0.f;
            __half hi, lo; split16(v, hi, lo);
            dh[k] = hi; dl[k] = lo;
        }
    }
}

__global__ void conv_w_kernel(const float* __restrict__ wih, const float* __restrict__ whh) {
    int r = blockIdx.x;  // 0..1535
    for (int k = threadIdx.x; k < INPAD; k += blockDim.x) {
        float v = (k < INDIM) ? wih[(size_t)r * INDIM + k] : 0.f;
        __half hi, lo; split16(v, hi, lo);
        d_Wih_hi[(size_t)r * INPAD + k] = hi;
        d_Wih_lo[(size_t)r * INPAD + k] = lo;
    }
    for (int k = threadIdx.x; k < HDIM; k += blockDim.x) {
        float v = whh[(size_t)r * HDIM + k];
        __half hi, lo; split16(v, hi, lo);
        d_Whh_hi[(size_t)r * HDIM + k] = hi;
        d_Whh_lo[(size_t)r * HDIM + k] = lo;
    }
}

__global__ void init_kernel() {
    int idx = blockIdx.x * blockDim.x + threadIdx.x;
    if (idx == 0) d_bar = 0u;
    uint4 z = make_uint4(0u, 0u, 0u, 0u);
    int n = (BSZ * HDIM) / 8;
    uint4* p0 = (uint4*)d_hhi[0];
    uint4* p1 = (uint4*)d_hlo[0];
    for (int i = idx; i < n; i += gridDim.x * blockDim.x) { p0[i] = z; p1[i] = z; }
}

// ---------------- IG GEMM (split fp16): [BT x 304] @ [304 x 1536]^T --------
// CTA tile 64(M) x 128(N), 8 warps (2x4), warp tile 32x32, 3-product split.
#define IGS 24  // smem row stride (halves), padded
__global__ void __launch_bounds__(256) gemm_ig_kernel(const float* __restrict__ bias) {
    __shared__ __half Ashi[64 * IGS], Aslo[64 * IGS];
    __shared__ __half Bshi[128 * IGS], Bslo[128 * IGS];
    const int tid = threadIdx.x;
    const int warp = tid >> 5, lane = tid & 31;
    const int g = lane >> 2, tg = lane & 3;
    const int m0 = blockIdx.y * 64;
    const int n0 = blockIdx.x * 128;
    const int wm = (warp & 1) * 32;
    const int wn = (warp >> 1) * 32;

    float acc[2][4][4];
#pragma unroll
    for (int i = 0; i < 2; i++)
#pragma unroll
        for (int j = 0; j < 4; j++)
#pragma unroll
            for (int e = 0; e < 4; e++) acc[i][j][e] = 0.f;

    for (int ko = 0; ko < INPAD; ko += 16) {
        if (tid < 128) {
            int row = tid >> 1, seg = tid & 1;
            size_t src = (size_t)(m0 + row) * INPAD + ko + seg * 8;
            *(uint4*)&Ashi[row * IGS + seg * 8] = *(const uint4*)&d_Xhi[src];
            *(uint4*)&Aslo[row * IGS + seg * 8] = *(const uint4*)&d_Xlo[src];
        }
        {
            int row = tid >> 1, seg = tid & 1;
            size_t src = (size_t)(n0 + row) * INPAD + ko + seg * 8;
            *(uint4*)&Bshi[row * IGS + seg * 8] = *(const uint4*)&d_Wih_hi[src];
            *(uint4*)&Bslo[row * IGS + seg * 8] = *(const uint4*)&d_Wih_lo[src];
        }
        __syncthreads();

        uint32_t ah[2][4], al[2][4];
#pragma unroll
        for (int i = 0; i < 2; i++) {
            int r = wm + i * 16 + g;
            ah[i][0] = *(const uint32_t*)&Ashi[r * IGS + tg * 2];
            ah[i][1] = *(const uint32_t*)&Ashi[(r + 8) * IGS + tg * 2];
            ah[i][2] = *(const uint32_t*)&Ashi[r * IGS + tg * 2 + 8];
            ah[i][3] = *(const uint32_t*)&Ashi[(r + 8) * IGS + tg * 2 + 8];
            al[i][0] = *(const uint32_t*)&Aslo[r * IGS + tg * 2];
            al[i][1] = *(const uint32_t*)&Aslo[(r + 8) * IGS + tg * 2];
            al[i][2] = *(const uint32_t*)&Aslo[r * IGS + tg * 2 + 8];
            al[i][3] = *(const uint32_t*)&Aslo[(r + 8) * IGS + tg * 2 + 8];
        }
#pragma unroll
        for (int j = 0; j < 4; j++) {
            int n = wn + j * 8 + g;
            uint32_t bh0 = *(const uint32_t*)&Bshi[n * IGS + tg * 2];
            uint32_t bh1 = *(const uint32_t*)&Bshi[n * IGS + tg * 2 + 8];
            uint32_t bl0 = *(const uint32_t*)&Bslo[n * IGS + tg * 2];
            uint32_t bl1 = *(const uint32_t*)&Bslo[n * IGS + tg * 2 + 8];
#pragma unroll
            for (int i = 0; i < 2; i++) {
                mma16816(acc[i][j], ah[i], bh0, bh1);
                mma16816(acc[i][j], ah[i], bl0, bl1);
                mma16816(acc[i][j], al[i], bh0, bh1);
            }
        }
        __syncthreads();
    }

    // epilogue: add bias, scatter to IG[t][b][n] (m = b*1024 + t)
#pragma unroll
    for (int i = 0; i < 2; i++) {
#pragma unroll
        for (int j = 0; j < 4; j++) {
            int n = n0 + wn + j * 8 + tg * 2;
            float bb0 = bias[n], bb1 = bias[n + 1];
            int m = m0 + wm + i * 16 + g;
            {
                int tt = m & 1023, bi = m >> 10;
                *(float2*)&d_IG[((size_t)tt * BSZ + bi) * GDIM + n] =
                    make_float2(acc[i][j][0] + bb0, acc[i][j][1] + bb1);
            }
            {
                int m2 = m + 8;
                int tt = m2 & 1023, bi = m2 >> 10;
                *(float2*)&d_IG[((size_t)tt * BSZ + bi) * GDIM + n] =
                    make_float2(acc[i][j][2] + bb0, acc[i][j][3] + bb1);
            }
        }
    }
}

// ---------------- persistent GRU scan (split fp16, W resident in smem) -----
// 64 CTAs: mb = blockIdx.x&3 (64 batch rows), nb = blockIdx.x>>2 (32 h-cols).
// 256 threads = 8 warps: wm = warp&1 (32 rows), wn = warp>>1 (8 h-cols x 3 gates).
#define SCAN_CTAS 64
#define WST 520   // W smem row stride (halves)
#define AST 40    // A smem row stride (halves)
#define SCAN_SMEM ((2 * 96 * WST + 2 * 64 * AST) * 2)  // bytes = 209920

extern __shared__ __half smem_scan[];

__global__ void __launch_bounds__(256) scan_kernel(const float* __restrict__ b_n_p) {
    __half* Whi = smem_scan;               // 96 x WST
    __half* Wlo = Whi + 96 * WST;
    __half* Ahi = Wlo + 96 * WST;          // 64 x AST
    __half* Alo = Ahi + 64 * AST;

    const int tid = threadIdx.x;
    const int warp = tid >> 5, lane = tid & 31;
    const int g = lane >> 2, tg = lane & 3;
    const int wm = warp & 1, wn = warp >> 1;
    const int mb = blockIdx.x & 3;
    const int nb = blockIdx.x >> 2;

    // Load resident W_hh tile: 96 rows (3 gates x 32 h-cols) x 512 k, hi+lo.
    for (int idx = tid; idx < 96 * 64; idx += 256) {
        int row = idx >> 6, seg = idx & 63;
        int gate = row >> 5, wi = row & 31;
        size_t src = (size_t)((gate << 9) + nb * 32 + wi) * HDIM + seg * 8;
        *(uint4*)&Whi[row * WST + seg * 8] = *(const uint4*)&d_Whh_hi[src];
        *(uint4*)&Wlo[row * WST + seg * 8] = *(const uint4*)&d_Whh_lo[src];
    }
    __syncthreads();

    const int hc = nb * 32 + wn * 8 + tg * 2;  // this thread's h-column base
    float bn0 = b_n_p[hc], bn1 = b_n_p[hc + 1];

    float hreg[2][2][2];
#pragma unroll
    for (int i = 0; i < 2; i++)
#pragma unroll
        for (int hh = 0; hh < 2; hh++) { hreg[i][hh][0] = 0.f; hreg[i][hh][1] = 0.f; }

    for (int t = 0; t < TLEN; t++) {
        const __half* hinh = d_hhi[t & 1];
        const __half* hinl = d_hlo[t & 1];
        __half* houth = d_hhi[(t + 1) & 1];
        __half* houtl = d_hlo[(t + 1) & 1];

        float acc[3][2][4];
#pragma unroll
        for (int gt = 0; gt < 3; gt++)
#pragma unroll
            for (int i = 0; i < 2; i++)
#pragma unroll
                for (int e = 0; e < 4; e++) acc[gt][i][e] = 0.f;

        for (int ko = 0; ko < HDIM; ko += 32) {
            {   // A tile: 64 rows x 32 k, hi+lo (one uint4 each per thread)
                int row = tid >> 2, seg = tid & 3;
                size_t src = (size_t)(mb * 64 + row) * HDIM + ko + seg * 8;
                *(uint4*)&Ahi[row * AST + seg * 8] = __ldcg((const uint4*)&hinh[src]);
                *(uint4*)&Alo[row * AST + seg * 8] = __ldcg((const uint4*)&hinl[src]);
            }
            __syncthreads();

#pragma unroll
            for (int kk = 0; kk < 32; kk += 16) {
                uint32_t ah[2][4], al[2][4];
#pragma unroll
                for (int i = 0; i < 2; i++) {
                    int r = wm * 32 + i * 16 + g;
                    ah[i][0] = *(const uint32_t*)&Ahi[r * AST + kk + tg * 2];
                    ah[i][1] = *(const uint32_t*)&Ahi[(r + 8) * AST + kk + tg * 2];
                    ah[i][2] = *(const uint32_t*)&Ahi[r * AST + kk + tg * 2 + 8];
                    ah[i][3] = *(const uint32_t*)&Ahi[(r + 8) * AST + kk + tg * 2 + 8];
                    al[i][0] = *(const uint32_t*)&Alo[r * AST + kk + tg * 2];
                    al[i][1] = *(const uint32_t*)&Alo[(r + 8) * AST + kk + tg * 2];
                    al[i][2] = *(const uint32_t*)&Alo[r * AST + kk + tg * 2 + 8];
                    al[i][3] = *(const uint32_t*)&Alo[(r + 8) * AST + kk + tg * 2 + 8];
                }
#pragma unroll
                for (int gate = 0; gate < 3; gate++) {
                    int n = gate * 32 + wn * 8 + g;
                    uint32_t bh0 = *(const uint32_t*)&Whi[n * WST + ko + kk + tg * 2];
                    uint32_t bh1 = *(const uint32_t*)&Whi[n * WST + ko + kk + tg * 2 + 8];
                    uint32_t bl0 = *(const uint32_t*)&Wlo[n * WST + ko + kk + tg * 2];
                    uint32_t bl1 = *(const uint32_t*)&Wlo[n * WST + ko + kk + tg * 2 + 8];
#pragma unroll
                    for (int i = 0; i < 2; i++) {
                        mma16816(acc[gate][i], ah[i], bh0, bh1);
                        mma16816(acc[gate][i], ah[i], bl0, bl1);
                        mma16816(acc[gate][i], al[i], bh0, bh1);
                    }
                }
            }
            __syncthreads();
        }

        // epilogue: gates + hidden update (h_old in registers)
#pragma unroll
        for (int i = 0; i < 2; i++) {
#pragma unroll
            for (int hh = 0; hh < 2; hh++) {
                int bb = mb * 64 + wm * 32 + i * 16 + g + hh * 8;
                size_t ib = ((size_t)t * BSZ + bb) * GDIM + hc;
                float2 igr = *(const float2*)&d_IG[ib];
                float2 igz = *(const float2*)&d_IG[ib + 512];
                float2 ign = *(const float2*)&d_IG[ib + 1024];
                float hv[2];
#pragma unroll
                for (int cb = 0; cb < 2; cb++) {
                    float ir  = cb ? igr.y : igr.x;
                    float iz  = cb ? igz.y : igz.x;
                    float inn = cb ? ign.y : ign.x;
                    float bn  = cb ? bn1 : bn0;
                    float rg = my_sig(ir + acc[0][i][hh * 2 + cb]);
                    float zg = my_sig(iz + acc[1][i][hh * 2 + cb]);
                    float ng = my_tanh(inn + rg * (acc[2][i][hh * 2 + cb] + bn));
                    float v = ng + zg * (hreg[i][hh][cb] - ng);
                    hreg[i][hh][cb] = v;
                    hv[cb] = v;
                }
                __half h0, l0, h1, l1;
                split16(hv[0], h0, l0);
                split16(hv[1], h1, l1);
                *(__half2*)&houth[bb * HDIM + hc] = __halves2half2(h0, h1);
                *(__half2*)&houtl[bb * HDIM + hc] = __halves2half2(l0, l1);
                if (t == TLEN - 1)
                    *(float2*)&d_hfinal[bb * HDIM + hc] = make_float2(hv[0], hv[1]);
            }
        }

        // device-wide generation barrier (monotonic counter)
        if (t < TLEN - 1) {
            __threadfence();
            __syncthreads();
            if (tid == 0) {
                atomicAdd(&d_bar, 1u);
                unsigned tgt = (unsigned)SCAN_CTAS * (unsigned)(t + 1);
                volatile unsigned* p = &d_bar;
                while (*p < tgt) { }
                __threadfence();
            }
            __syncthreads();
        }
    }
}

// ---------------- tail: dropout (partitionable threefry) + LN + MLP --------
// JAX partitionable path: bits(i) = b1 ^ b2 of threefry2x32(key=(0,42), (0, i));
// keep = u < 0.5  <=>  top bit of bits == 0 (exact).
__global__ void __launch_bounds__(256) tail_kernel(
    const float* __restrict__ ln_w, const float* __restrict__ ln_b,
    const float* __restrict__ w1, const float* __restrict__ b1,
    const float* __restrict__ w2, const float* __restrict__ ob,
    float* __restrict__ out) {
    __shared__ float hs[512];
    __shared__ float r1[256], r2[256];
    const int bidx = blockIdx.x, tid = threadIdx.x;

    float s = 0.f, q = 0.f;
    for (int k = tid; k < 512; k += 256) {
        int i = bidx * 512 + k;
        uint2 o = threefry_0_42(0u, (uint32_t)i);
        uint32_t bits = o.x ^ o.y;
        float v = (bits >> 31) ? 0.f : d_hfinal[i] * 2.0f;
        hs[k] = v;
        s += v;
        q += v * v;
    }
    r1[tid] = s; r2[tid] = q;
    __syncthreads();
    for (int off = 128; off > 0; off >>= 1) {
        if (tid < off) { r1[tid] += r1[tid + off]; r2[tid] += r2[tid + off]; }
        __syncthreads();
    }
    float mu = r1[0] * (1.f / 512.f);
    float var = r2[0] * (1.f / 512.f) - mu * mu;
    float rstd = rsqrtf(var + 1e-5f);
    __syncthreads();
    for (int k = tid; k < 512; k += 256)
        hs[k] = (hs[k] - mu) * rstd * ln_w[k] + ln_b[k];
    __syncthreads();

    float a1 = b1[tid];
    const float* wrow = w1 + (size_t)tid * 512;
#pragma unroll 8
    for (int k = 0; k < 512; k++) a1 = fmaf(hs[k], wrow[k], a1);

    float p0 = a1 * w2[tid];
    float p1 = a1 * w2[256 + tid];
    __syncthreads();
    r1[tid] = p0; r2[tid] = p1;
    __syncthreads();
    for (int off = 128; off > 0; off >>= 1) {
        if (tid < off) { r1[tid] += r1[tid + off]; r2[tid] += r2[tid + off]; }
        __syncthreads();
    }
    if (tid == 0) {
        out[bidx * 2 + 0] = my_sig(r1[0] + ob[0]);
        out[bidx * 2 + 1] = my_sig(r2[0] + ob[1]);
    }
}

// ---------------- launcher --------------------------------------------------
extern "C" void kernel_launch(void* const* d_in, const int* in_sizes, int n_in,
                              void* d_out, int out_size) {
    const float* x     = (const float*)d_in[0];
    const float* w_ih  = (const float*)d_in[1];
    const float* w_hh  = (const float*)d_in[2];
    const float* b     = (const float*)d_in[3];
    const float* b_n   = (const float*)d_in[4];
    const float* ln_w  = (const float*)d_in[5];
    const float* ln_b  = (const float*)d_in[6];
    const float* w1    = (const float*)d_in[7];
    const float* b1    = (const float*)d_in[8];
    const float* w2    = (const float*)d_in[9];
    const float* ob    = (const float*)d_in[10];
    float* out = (float*)d_out;

    cudaFuncSetAttribute(scan_kernel, cudaFuncAttributeMaxDynamicSharedMemorySize, SCAN_SMEM);

    conv_x_kernel<<<BT / 8, 128>>>(x);
    conv_w_kernel<<<GDIM, 128>>>(w_ih, w_hh);
    init_kernel<<<64, 256>>>();
    gemm_ig_kernel<<<dim3(GDIM / 128, BT / 64), 256>>>(b);
    scan_kernel<<<SCAN_CTAS, 256, SCAN_SMEM>>>(b_n);
    tail_kernel<<<BSZ, 256>>>(ln_w, ln_b, w1, b1, w2, ob, out);
}

// round 14
// speedup vs baseline: 2.6278x; 1.8573x over previous
#include <cuda_runtime.h>
#include <cuda_fp16.h>
#include <cuda_bf16.h>
#include <cstdint>

// Problem sizes
#define BSZ   256
#define TLEN  1024
#define INDIM 302
#define INPAD 304            // padded K (mult of 16)
#define HDIM  512
#define GDIM  1536           // 3*H
#define BT    (BSZ*TLEN)     // 262144

// ---------------- device scratch (static; no cudaMalloc) -------------------
static __device__ __half   d_Xhi[(size_t)BT * INPAD];
static __device__ __half   d_Xlo[(size_t)BT * INPAD];
static __device__ __half   d_Wih_hi[(size_t)GDIM * INPAD];
static __device__ __half   d_Wih_lo[(size_t)GDIM * INPAD];
static __device__ __half   d_Whh_hi[(size_t)GDIM * HDIM];
static __device__ __half   d_Whh_lo[(size_t)GDIM * HDIM];
static __device__ float    d_IG[(size_t)TLEN * BSZ * GDIM];    // [T][B][3H]
static __device__ __half   d_hhi[2][BSZ * HDIM];
static __device__ __half   d_hlo[2][BSZ * HDIM];
static __device__ float    d_hfinal[BSZ * HDIM];
static __device__ unsigned d_bar;

// ---------------- cp.async helpers (cg = L2-only: cross-CTA coherent) ------
__device__ __forceinline__ void cpa16(uint32_t dst, const void* src) {
    asm volatile("cp.async.cg.shared.global [%0], [%1], 16;" :: "r"(dst), "l"(src));
}
__device__ __forceinline__ void cpa_commit() { asm volatile("cp.async.commit_group;"); }
__device__ __forceinline__ void cpa_wait0()  { asm volatile("cp.async.wait_group 0;"); }
__device__ __forceinline__ void cpa_wait1()  { asm volatile("cp.async.wait_group 1;"); }

// ---------------- fast MUFU gates (EX2/RCP, err ~1e-7 abs) ------------------
__device__ __forceinline__ float fast_sig(float x) {
    float e, r;
    asm("ex2.approx.ftz.f32 %0, %1;" : "=f"(e) : "f"(x * -1.4426950408889634f));
    asm("rcp.approx.ftz.f32 %0, %1;" : "=f"(r) : "f"(e + 1.0f));
    return r;
}
__device__ __forceinline__ float fast_tanh(float x) {
    float e, r;
    asm("ex2.approx.ftz.f32 %0, %1;" : "=f"(e) : "f"(x * 2.8853900817779268f));  // e^{2x}
    asm("rcp.approx.ftz.f32 %0, %1;" : "=f"(r) : "f"(e + 1.0f));
    return fmaf(-2.0f, r, 1.0f);                         // (e^{2x}-1)/(e^{2x}+1)
}

// ---------------- accurate exp/sig for the tail -----------------------------
__device__ __forceinline__ float my_exp(float x) {
    x = fminf(fmaxf(x, -87.0f), 87.0f);
    float n = rintf(x * 1.44269504088896341f);
    float r = fmaf(n, -0.693145751953125f, x);
    r = fmaf(n, -1.4286067653e-6f, r);
    float p = 1.9841269841e-4f;
    p = fmaf(p, r, 1.3888888889e-3f);
    p = fmaf(p, r, 8.3333333333e-3f);
    p = fmaf(p, r, 4.1666666667e-2f);
    p = fmaf(p, r, 1.6666666667e-1f);
    p = fmaf(p, r, 5.0e-1f);
    p = fmaf(p, r, 1.0f);
    p = fmaf(p, r, 1.0f);
    float s = __int_as_float(((int)n + 127) << 23);
    return p * s;
}
__device__ __forceinline__ float my_sig(float x) {
    return __fdiv_rn(1.0f, 1.0f + my_exp(-x));
}

// ---------------- mma.sync m16n8k16 fp16->fp32 -----------------------------
__device__ __forceinline__ void mma16816(float* c, const uint32_t* a, uint32_t b0, uint32_t b1) {
    asm volatile(
        "mma.sync.aligned.m16n8k16.row.col.f32.f16.f16.f32 "
        "{%0,%1,%2,%3}, {%4,%5,%6,%7}, {%8,%9}, {%0,%1,%2,%3};\n"
        : "+f"(c[0]), "+f"(c[1]), "+f"(c[2]), "+f"(c[3])
        : "r"(a[0]), "r"(a[1]), "r"(a[2]), "r"(a[3]), "r"(b0), "r"(b1));
}

// ---------------- threefry2x32 with key (0, 42) ----------------------------
__device__ __forceinline__ uint2 threefry_0_42(uint32_t x0, uint32_t x1) {
    const uint32_t k0 = 0u, k1 = 42u;
    const uint32_t k2 = k0 ^ k1 ^ 0x1BD11BDAu;
    const uint32_t ks[3] = {k0, k1, k2};
    const int rotA[4] = {13, 15, 26, 6};
    const int rotB[4] = {17, 29, 16, 24};
    x0 += ks[0]; x1 += ks[1];
#pragma unroll
    for (int i = 0; i < 5; i++) {
        const int* r = (i & 1) ? rotB : rotA;
#pragma unroll
        for (int j = 0; j < 4; j++) {
            x0 += x1;
            x1 = (x1 << r[j]) | (x1 >> (32 - r[j]));
            x1 ^= x0;
        }
        x0 += ks[(i + 1) % 3];
        x1 += ks[(i + 2) % 3] + (uint32_t)(i + 1);
    }
    return make_uint2(x0, x1);
}

// ---------------- split helpers --------------------------------------------
__device__ __forceinline__ void split16(float v, __half& hi, __half& lo) {
    hi = __float2half(v);
    lo = __float2half(v - __half2float(hi));
}

// ---------------- conversion kernels ---------------------------------------
__global__ void conv_x_kernel(const float* __restrict__ x) {
    int m0 = blockIdx.x * 8;
#pragma unroll
    for (int r = 0; r < 8; r++) {
        int m = m0 + r;
        const float* src = x + (size_t)m * INDIM;
        __half* dh = d_Xhi + (size_t)m * INPAD;
        __half* dl = d_Xlo + (size_t)m * INPAD;
        for (int k = threadIdx.x; k < INPAD; k += blockDim.x) {
            float v = (k < INDIM) ? src[k] : 0.f;
            __half hi, lo; split16(v, hi, lo);
            dh[k] = hi; dl[k] = lo;
        }
    }
}

__global__ void conv_w_kernel(const float* __restrict__ wih, const float* __restrict__ whh) {
    int r = blockIdx.x;  // 0..1535
    for (int k = threadIdx.x; k < INPAD; k += blockDim.x) {
        float v = (k < INDIM) ? wih[(size_t)r * INDIM + k] : 0.f;
        __half hi, lo; split16(v, hi, lo);
        d_Wih_hi[(size_t)r * INPAD + k] = hi;
        d_Wih_lo[(size_t)r * INPAD + k] = lo;
    }
    for (int k = threadIdx.x; k < HDIM; k += blockDim.x) {
        float v = whh[(size_t)r * HDIM + k];
        __half hi, lo; split16(v, hi, lo);
        d_Whh_hi[(size_t)r * HDIM + k] = hi;
        d_Whh_lo[(size_t)r * HDIM + k] = lo;
    }
}

__global__ void init_kernel() {
    int idx = blockIdx.x * blockDim.x + threadIdx.x;
    if (idx == 0) d_bar = 0u;
    uint4 z = make_uint4(0u, 0u, 0u, 0u);
    int n = (BSZ * HDIM) / 8;
    uint4* p0 = (uint4*)d_hhi[0];
    uint4* p1 = (uint4*)d_hlo[0];
    for (int i = idx; i < n; i += gridDim.x * blockDim.x) { p0[i] = z; p1[i] = z; }
}

// ---------------- IG GEMM (split fp16, 2-stage cp.async) -------------------
// CTA tile 64(M) x 128(N), 8 warps (2x4), warp tile 32x32, 3-product split.
#define IGS 24  // smem row stride (halves), padded
__global__ void __launch_bounds__(256) gemm_ig_kernel(const float* __restrict__ bias) {
    __shared__ __half Ashi[2][64 * IGS], Aslo[2][64 * IGS];
    __shared__ __half Bshi[2][128 * IGS], Bslo[2][128 * IGS];
    const int tid = threadIdx.x;
    const int warp = tid >> 5, lane = tid & 31;
    const int g = lane >> 2, tg = lane & 3;
    const int m0 = blockIdx.y * 64;
    const int n0 = blockIdx.x * 128;
    const int wm = (warp & 1) * 32;
    const int wn = (warp >> 1) * 32;

    const uint32_t sa_hi = (uint32_t)__cvta_generic_to_shared(&Ashi[0][0]);
    const uint32_t sa_lo = (uint32_t)__cvta_generic_to_shared(&Aslo[0][0]);
    const uint32_t sb_hi = (uint32_t)__cvta_generic_to_shared(&Bshi[0][0]);
    const uint32_t sb_lo = (uint32_t)__cvta_generic_to_shared(&Bslo[0][0]);

    float acc[2][4][4];
#pragma unroll
    for (int i = 0; i < 2; i++)
#pragma unroll
        for (int j = 0; j < 4; j++)
#pragma unroll
            for (int e = 0; e < 4; e++) acc[i][j][e] = 0.f;

    // per-stage loads: A by tid<128 (row=tid>>1, seg=tid&1), B by all 256
    auto load_stage = [&](int kt, int s) {
        int ko = kt * 16;
        uint32_t soff = (uint32_t)s * (64 * IGS * 2);
        uint32_t boff = (uint32_t)s * (128 * IGS * 2);
        if (tid < 128) {
            int row = tid >> 1, seg = tid & 1;
            size_t src = (size_t)(m0 + row) * INPAD + ko + seg * 8;
            uint32_t d = (uint32_t)(row * IGS + seg * 8) * 2;
            cpa16(sa_hi + soff + d, &d_Xhi[src]);
            cpa16(sa_lo + soff + d, &d_Xlo[src]);
        }
        {
            int row = tid >> 1, seg = tid & 1;
            size_t src = (size_t)(n0 + row) * INPAD + ko + seg * 8;
            uint32_t d = (uint32_t)(row * IGS + seg * 8) * 2;
            cpa16(sb_hi + boff + d, &d_Wih_hi[src]);
            cpa16(sb_lo + boff + d, &d_Wih_lo[src]);
        }
    };

    load_stage(0, 0);
    cpa_commit();

    for (int kt = 0; kt < 19; kt++) {
        int s = kt & 1;
        if (kt < 18) { load_stage(kt + 1, s ^ 1); cpa_commit(); }
        if (kt < 18) cpa_wait1(); else cpa_wait0();
        __syncthreads();

        uint32_t ah[2][4], al[2][4];
#pragma unroll
        for (int i = 0; i < 2; i++) {
            int r = wm + i * 16 + g;
            ah[i][0] = *(const uint32_t*)&Ashi[s][r * IGS + tg * 2];
            ah[i][1] = *(const uint32_t*)&Ashi[s][(r + 8) * IGS + tg * 2];
            ah[i][2] = *(const uint32_t*)&Ashi[s][r * IGS + tg * 2 + 8];
            ah[i][3] = *(const uint32_t*)&Ashi[s][(r + 8) * IGS + tg * 2 + 8];
            al[i][0] = *(const uint32_t*)&Aslo[s][r * IGS + tg * 2];
            al[i][1] = *(const uint32_t*)&Aslo[s][(r + 8) * IGS + tg * 2];
            al[i][2] = *(const uint32_t*)&Aslo[s][r * IGS + tg * 2 + 8];
            al[i][3] = *(const uint32_t*)&Aslo[s][(r + 8) * IGS + tg * 2 + 8];
        }
#pragma unroll
        for (int j = 0; j < 4; j++) {
            int n = wn + j * 8 + g;
            uint32_t bh0 = *(const uint32_t*)&Bshi[s][n * IGS + tg * 2];
            uint32_t bh1 = *(const uint32_t*)&Bshi[s][n * IGS + tg * 2 + 8];
            uint32_t bl0 = *(const uint32_t*)&Bslo[s][n * IGS + tg * 2];
            uint32_t bl1 = *(const uint32_t*)&Bslo[s][n * IGS + tg * 2 + 8];
#pragma unroll
            for (int i = 0; i < 2; i++) {
                mma16816(acc[i][j], ah[i], bh0, bh1);
                mma16816(acc[i][j], ah[i], bl0, bl1);
                mma16816(acc[i][j], al[i], bh0, bh1);
            }
        }
        __syncthreads();
    }

    // epilogue: add bias, scatter to IG[t][b][n] (m = b*1024 + t)
#pragma unroll
    for (int i = 0; i < 2; i++) {
#pragma unroll
        for (int j = 0; j < 4; j++) {
            int n = n0 + wn + j * 8 + tg * 2;
            float bb0 = bias[n], bb1 = bias[n + 1];
            int m = m0 + wm + i * 16 + g;
            {
                int tt = m & 1023, bi = m >> 10;
                *(float2*)&d_IG[((size_t)tt * BSZ + bi) * GDIM + n] =
                    make_float2(acc[i][j][0] + bb0, acc[i][j][1] + bb1);
            }
            {
                int m2 = m + 8;
                int tt = m2 & 1023, bi = m2 >> 10;
                *(float2*)&d_IG[((size_t)tt * BSZ + bi) * GDIM + n] =
                    make_float2(acc[i][j][2] + bb0, acc[i][j][3] + bb1);
            }
        }
    }
}

// ---------------- persistent GRU scan (split fp16, 128 CTAs) ---------------
// 128 CTAs: mb = blockIdx.x&7 (32 batch rows), nb = blockIdx.x>>3 (32 h-cols).
// 8 warps: wm = warp&1 (16 rows), wn = warp>>1 (8 h-cols x 3 gates).
// W_hh tile (96x512 hi+lo) resident in smem; A tile 2-stage cp.async.cg (L2).
#define SCAN_CTAS 128
#define WST 520   // W smem row stride (halves)
#define AST 40    // A smem row stride (halves)
#define SCAN_SMEM ((2 * 96 * WST + 2 * 2 * 32 * AST) * 2)  // 209920 bytes

extern __shared__ __half smem_scan[];

__global__ void __launch_bounds__(256) scan_kernel(const float* __restrict__ b_n_p) {
    __half* Whi = smem_scan;               // 96 x WST
    __half* Wlo = Whi + 96 * WST;
    __half* Abase = Wlo + 96 * WST;        // 2 stages x (32 hi + 32 lo) x AST
    const uint32_t Abase_u32 = (uint32_t)__cvta_generic_to_shared(Abase);

    const int tid = threadIdx.x;
    const int warp = tid >> 5, lane = tid & 31;
    const int g = lane >> 2, tg = lane & 3;
    const int wm = warp & 1, wn = warp >> 1;
    const int mb = blockIdx.x & 7;
    const int nb = blockIdx.x >> 3;

    // Load resident W_hh tile: 96 rows (3 gates x 32 h-cols) x 512 k, hi+lo.
    for (int idx = tid; idx < 96 * 64; idx += 256) {
        int row = idx >> 6, seg = idx & 63;
        int gate = row >> 5, wi = row & 31;
        size_t src = (size_t)((gate << 9) + nb * 32 + wi) * HDIM + seg * 8;
        *(uint4*)&Whi[row * WST + seg * 8] = *(const uint4*)&d_Whh_hi[src];
        *(uint4*)&Wlo[row * WST + seg * 8] = *(const uint4*)&d_Whh_lo[src];
    }
    __syncthreads();

    const int hc = nb * 32 + wn * 8 + tg * 2;
    float bn0 = b_n_p[hc], bn1 = b_n_p[hc + 1];

    float hreg[2][2];                      // [hh][cb]
#pragma unroll
    for (int hh = 0; hh < 2; hh++) { hreg[hh][0] = 0.f; hreg[hh][1] = 0.f; }

    // per-stage A load: 1 cp.async per thread (tid<128: hi; else lo)
    const int a_half = tid >> 7;           // 0 = hi, 1 = lo
    const int a_id = tid & 127;
    const int a_row = a_id >> 2, a_seg = a_id & 3;

    for (int t = 0; t < TLEN; t++) {
        const __half* hinh = d_hhi[t & 1];
        const __half* hinl = d_hlo[t & 1];
        __half* houth = d_hhi[(t + 1) & 1];
        __half* houtl = d_hlo[(t + 1) & 1];
        const __half* a_src_base = a_half ? hinl : hinh;

        float acc[3][4];
#pragma unroll
        for (int gt = 0; gt < 3; gt++)
#pragma unroll
            for (int e = 0; e < 4; e++) acc[gt][e] = 0.f;

        // prologue: stage 0
        {
            const __half* src = a_src_base + (size_t)(mb * 32 + a_row) * HDIM + a_seg * 8;
            uint32_t dst = Abase_u32 + (uint32_t)((a_half * 32 + a_row) * AST + a_seg * 8) * 2;
            cpa16(dst, src);
            cpa_commit();
        }

        for (int koi = 0; koi < 16; koi++) {
            int s = koi & 1;
            int kb = koi * 32;
            if (koi < 15) {
                const __half* src = a_src_base + (size_t)(mb * 32 + a_row) * HDIM + (kb + 32) + a_seg * 8;
                uint32_t dst = Abase_u32 +
                    (uint32_t)(((s ^ 1) * 64 + a_half * 32 + a_row) * AST + a_seg * 8) * 2;
                cpa16(dst, src);
                cpa_commit();
                cpa_wait1();
            } else {
                cpa_wait0();
            }
            __syncthreads();

            const __half* Ah = Abase + s * 64 * AST;
            const __half* Al = Ah + 32 * AST;
#pragma unroll
            for (int kk = 0; kk < 32; kk += 16) {
                uint32_t ah[4], al[4];
                int r = wm * 16 + g;
                ah[0] = *(const uint32_t*)&Ah[r * AST + kk + tg * 2];
                ah[1] = *(const uint32_t*)&Ah[(r + 8) * AST + kk + tg * 2];
                ah[2] = *(const uint32_t*)&Ah[r * AST + kk + tg * 2 + 8];
                ah[3] = *(const uint32_t*)&Ah[(r + 8) * AST + kk + tg * 2 + 8];
                al[0] = *(const uint32_t*)&Al[r * AST + kk + tg * 2];
                al[1] = *(const uint32_t*)&Al[(r + 8) * AST + kk + tg * 2];
                al[2] = *(const uint32_t*)&Al[r * AST + kk + tg * 2 + 8];
                al[3] = *(const uint32_t*)&Al[(r + 8) * AST + kk + tg * 2 + 8];
#pragma unroll
                for (int gate = 0; gate < 3; gate++) {
                    int n = gate * 32 + wn * 8 + g;
                    uint32_t bh0 = *(const uint32_t*)&Whi[n * WST + kb + kk + tg * 2];
                    uint32_t bh1 = *(const uint32_t*)&Whi[n * WST + kb + kk + tg * 2 + 8];
                    uint32_t bl0 = *(const uint32_t*)&Wlo[n * WST + kb + kk + tg * 2];
                    uint32_t bl1 = *(const uint32_t*)&Wlo[n * WST + kb + kk + tg * 2 + 8];
                    mma16816(acc[gate], ah, bh0, bh1);
                    mma16816(acc[gate], ah, bl0, bl1);
                    mma16816(acc[gate], al, bh0, bh1);
                }
            }
            __syncthreads();
        }

        // epilogue: gates (MUFU fast path) + hidden update (h_old in regs)
#pragma unroll
        for (int hh = 0; hh < 2; hh++) {
            int bb = mb * 32 + wm * 16 + g + hh * 8;
            size_t ib = ((size_t)t * BSZ + bb) * GDIM + hc;
            float2 igr = *(const float2*)&d_IG[ib];
            float2 igz = *(const float2*)&d_IG[ib + 512];
            float2 ign = *(const float2*)&d_IG[ib + 1024];
            float hv[2];
#pragma unroll
            for (int cb = 0; cb < 2; cb++) {
                float ir  = cb ? igr.y : igr.x;
                float iz  = cb ? igz.y : igz.x;
                float inn = cb ? ign.y : ign.x;
                float bn  = cb ? bn1 : bn0;
                float rg = fast_sig(ir + acc[0][hh * 2 + cb]);
                float zg = fast_sig(iz + acc[1][hh * 2 + cb]);
                float ng = fast_tanh(inn + rg * (acc[2][hh * 2 + cb] + bn));
                float v = ng + zg * (hreg[hh][cb] - ng);
                hreg[hh][cb] = v;
                hv[cb] = v;
            }
            __half h0, l0, h1, l1;
            split16(hv[0], h0, l0);
            split16(hv[1], h1, l1);
            *(__half2*)&houth[bb * HDIM + hc] = __halves2half2(h0, h1);
            *(__half2*)&houtl[bb * HDIM + hc] = __halves2half2(l0, l1);
            if (t == TLEN - 1)
                *(float2*)&d_hfinal[bb * HDIM + hc] = make_float2(hv[0], hv[1]);
        }

        // device-wide generation barrier (monotonic counter)
        if (t < TLEN - 1) {
            __threadfence();
            __syncthreads();
            if (tid == 0) {
                atomicAdd(&d_bar, 1u);
                unsigned tgt = (unsigned)SCAN_CTAS * (unsigned)(t + 1);
                volatile unsigned* p = &d_bar;
                while (*p < tgt) { }
                __threadfence();
            }
            __syncthreads();
        }
    }
}

// ---------------- tail: dropout (partitionable threefry) + LN + MLP --------
__global__ void __launch_bounds__(256) tail_kernel(
    const float* __restrict__ ln_w, const float* __restrict__ ln_b,
    const float* __restrict__ w1, const float* __restrict__ b1,
    const float* __restrict__ w2, const float* __restrict__ ob,
    float* __restrict__ out) {
    __shared__ float hs[512];
    __shared__ float r1[256], r2[256];
    const int bidx = blockIdx.x, tid = threadIdx.x;

    float s = 0.f, q = 0.f;
    for (int k = tid; k < 512; k += 256) {
        int i = bidx * 512 + k;
        uint2 o = threefry_0_42(0u, (uint32_t)i);
        uint32_t bits = o.x ^ o.y;
        float v = (bits >> 31) ? 0.f : d_hfinal[i] * 2.0f;
        hs[k] = v;
        s += v;
        q += v * v;
    }
    r1[tid] = s; r2[tid] = q;
    __syncthreads();
    for (int off = 128; off > 0; off >>= 1) {
        if (tid < off) { r1[tid] += r1[tid + off]; r2[tid] += r2[tid + off]; }
        __syncthreads();
    }
    float mu = r1[0] * (1.f / 512.f);
    float var = r2[0] * (1.f / 512.f) - mu * mu;
    float rstd = rsqrtf(var + 1e-5f);
    __syncthreads();
    for (int k = tid; k < 512; k += 256)
        hs[k] = (hs[k] - mu) * rstd * ln_w[k] + ln_b[k];
    __syncthreads();

    float a1 = b1[tid];
    const float* wrow = w1 + (size_t)tid * 512;
#pragma unroll 8
    for (int k = 0; k < 512; k++) a1 = fmaf(hs[k], wrow[k], a1);

    float p0 = a1 * w2[tid];
    float p1 = a1 * w2[256 + tid];
    __syncthreads();
    r1[tid] = p0; r2[tid] = p1;
    __syncthreads();
    for (int off = 128; off > 0; off >>= 1) {
        if (tid < off) { r1[tid] += r1[tid + off]; r2[tid] += r2[tid + off]; }
        __syncthreads();
    }
    if (tid == 0) {
        out[bidx * 2 + 0] = my_sig(r1[0] + ob[0]);
        out[bidx * 2 + 1] = my_sig(r2[0] + ob[1]);
    }
}

// ---------------- launcher --------------------------------------------------
extern "C" void kernel_launch(void* const* d_in, const int* in_sizes, int n_in,
                              void* d_out, int out_size) {
    const float* x     = (const float*)d_in[0];
    const float* w_ih  = (const float*)d_in[1];
    const float* w_hh  = (const float*)d_in[2];
    const float* b     = (const float*)d_in[3];
    const float* b_n   = (const float*)d_in[4];
    const float* ln_w  = (const float*)d_in[5];
    const float* ln_b  = (const float*)d_in[6];
    const float* w1    = (const float*)d_in[7];
    const float* b1    = (const float*)d_in[8];
    const float* w2    = (const float*)d_in[9];
    const float* ob    = (const float*)d_in[10];
    float* out = (float*)d_out;

    cudaFuncSetAttribute(scan_kernel, cudaFuncAttributeMaxDynamicSharedMemorySize, SCAN_SMEM);

    conv_x_kernel<<<BT / 8, 128>>>(x);
    conv_w_kernel<<<GDIM, 128>>>(w_ih, w_hh);
    init_kernel<<<64, 256>>>();
    gemm_ig_kernel<<<dim3(GDIM / 128, BT / 64), 256>>>(b);
    scan_kernel<<<SCAN_CTAS, 256, SCAN_SMEM>>>(b_n);
    tail_kernel<<<BSZ, 256>>>(ln_w, ln_b, w1, b1, w2, ob, out);
}

// round 15
// speedup vs baseline: 4.0550x; 1.5431x over previous
#include <cuda_runtime.h>
#include <cuda_fp16.h>
#include <cuda_bf16.h>
#include <cstdint>

// Problem sizes
#define BSZ   256
#define TLEN  1024
#define INDIM 302
#define INPAD 304            // padded K (mult of 16)
#define HDIM  512
#define GDIM  1536           // 3*H
#define BT    (BSZ*TLEN)     // 262144

// ---------------- device scratch (static; no cudaMalloc) -------------------
static __device__ __half   d_Xh[(size_t)BT * INPAD];
static __device__ __half   d_Wih[(size_t)GDIM * INPAD];
static __device__ __half   d_Whh[(size_t)GDIM * HDIM];
static __device__ float    d_IG[(size_t)TLEN * BSZ * GDIM];    // [T][B][3H]
static __device__ __half   d_hh[2][BSZ * HDIM];                // fp16 hidden, double buffer
static __device__ float    d_hfinal[BSZ * HDIM];
static __device__ unsigned d_bar;

// ---------------- cp.async helpers (cg = L2-only: cross-CTA coherent) ------
__device__ __forceinline__ void cpa16(uint32_t dst, const void* src) {
    asm volatile("cp.async.cg.shared.global [%0], [%1], 16;" :: "r"(dst), "l"(src));
}
__device__ __forceinline__ void cpa_commit() { asm volatile("cp.async.commit_group;"); }
__device__ __forceinline__ void cpa_wait0()  { asm volatile("cp.async.wait_group 0;"); }
__device__ __forceinline__ void cpa_wait1()  { asm volatile("cp.async.wait_group 1;"); }

// ---------------- fast MUFU gates (EX2/RCP, err ~1e-7 abs) ------------------
__device__ __forceinline__ float fast_sig(float x) {
    float e, r;
    asm("ex2.approx.ftz.f32 %0, %1;" : "=f"(e) : "f"(x * -1.4426950408889634f));
    asm("rcp.approx.ftz.f32 %0, %1;" : "=f"(r) : "f"(e + 1.0f));
    return r;
}
__device__ __forceinline__ float fast_tanh(float x) {
    float e, r;
    asm("ex2.approx.ftz.f32 %0, %1;" : "=f"(e) : "f"(x * 2.8853900817779268f));  // e^{2x}
    asm("rcp.approx.ftz.f32 %0, %1;" : "=f"(r) : "f"(e + 1.0f));
    return fmaf(-2.0f, r, 1.0f);                         // (e^{2x}-1)/(e^{2x}+1)
}

// ---------------- accurate exp/sig for the tail -----------------------------
__device__ __forceinline__ float my_exp(float x) {
    x = fminf(fmaxf(x, -87.0f), 87.0f);
    float n = rintf(x * 1.44269504088896341f);
    float r = fmaf(n, -0.693145751953125f, x);
    r = fmaf(n, -1.4286067653e-6f, r);
    float p = 1.9841269841e-4f;
    p = fmaf(p, r, 1.3888888889e-3f);
    p = fmaf(p, r, 8.3333333333e-3f);
    p = fmaf(p, r, 4.1666666667e-2f);
    p = fmaf(p, r, 1.6666666667e-1f);
    p = fmaf(p, r, 5.0e-1f);
    p = fmaf(p, r, 1.0f);
    p = fmaf(p, r, 1.0f);
    float s = __int_as_float(((int)n + 127) << 23);
    return p * s;
}
__device__ __forceinline__ float my_sig(float x) {
    return __fdiv_rn(1.0f, 1.0f + my_exp(-x));
}

// ---------------- mma.sync m16n8k16 fp16->fp32 -----------------------------
__device__ __forceinline__ void mma16816(float* c, const uint32_t* a, uint32_t b0, uint32_t b1) {
    asm volatile(
        "mma.sync.aligned.m16n8k16.row.col.f32.f16.f16.f32 "
        "{%0,%1,%2,%3}, {%4,%5,%6,%7}, {%8,%9}, {%0,%1,%2,%3};\n"
        : "+f"(c[0]), "+f"(c[1]), "+f"(c[2]), "+f"(c[3])
        : "r"(a[0]), "r"(a[1]), "r"(a[2]), "r"(a[3]), "r"(b0), "r"(b1));
}

// ---------------- threefry2x32 with key (0, 42) ----------------------------
__device__ __forceinline__ uint2 threefry_0_42(uint32_t x0, uint32_t x1) {
    const uint32_t k0 = 0u, k1 = 42u;
    const uint32_t k2 = k0 ^ k1 ^ 0x1BD11BDAu;
    const uint32_t ks[3] = {k0, k1, k2};
    const int rotA[4] = {13, 15, 26, 6};
    const int rotB[4] = {17, 29, 16, 24};
    x0 += ks[0]; x1 += ks[1];
#pragma unroll
    for (int i = 0; i < 5; i++) {
        const int* r = (i & 1) ? rotB : rotA;
#pragma unroll
        for (int j = 0; j < 4; j++) {
            x0 += x1;
            x1 = (x1 << r[j]) | (x1 >> (32 - r[j]));
            x1 ^= x0;
        }
        x0 += ks[(i + 1) % 3];
        x1 += ks[(i + 2) % 3] + (uint32_t)(i + 1);
    }
    return make_uint2(x0, x1);
}

// ---------------- conversion kernels ---------------------------------------
__global__ void conv_x_kernel(const float* __restrict__ x) {
    int m0 = blockIdx.x * 8;
#pragma unroll
    for (int r = 0; r < 8; r++) {
        int m = m0 + r;
        const float* src = x + (size_t)m * INDIM;
        __half* dh = d_Xh + (size_t)m * INPAD;
        for (int k = threadIdx.x; k < INPAD; k += blockDim.x)
            dh[k] = __float2half((k < INDIM) ? src[k] : 0.f);
    }
}

__global__ void conv_w_kernel(const float* __restrict__ wih, const float* __restrict__ whh) {
    int r = blockIdx.x;  // 0..1535
    for (int k = threadIdx.x; k < INPAD; k += blockDim.x)
        d_Wih[(size_t)r * INPAD + k] = __float2half((k < INDIM) ? wih[(size_t)r * INDIM + k] : 0.f);
    for (int k = threadIdx.x; k < HDIM; k += blockDim.x)
        d_Whh[(size_t)r * HDIM + k] = __float2half(whh[(size_t)r * HDIM + k]);
}

__global__ void init_kernel() {
    int idx = blockIdx.x * blockDim.x + threadIdx.x;
    if (idx == 0) d_bar = 0u;
    uint4 z = make_uint4(0u, 0u, 0u, 0u);
    int n = (BSZ * HDIM) / 8;
    uint4* p0 = (uint4*)d_hh[0];
    for (int i = idx; i < n; i += gridDim.x * blockDim.x) p0[i] = z;
}

// ---------------- IG GEMM (plain fp16, 2-stage cp.async) -------------------
// CTA tile 64(M) x 128(N), 8 warps (2x4), warp tile 32x32.
#define IGS 24  // smem row stride (halves), padded
__global__ void __launch_bounds__(256) gemm_ig_kernel(const float* __restrict__ bias) {
    __shared__ __half As[2][64 * IGS];
    __shared__ __half Bs[2][128 * IGS];
    const int tid = threadIdx.x;
    const int warp = tid >> 5, lane = tid & 31;
    const int g = lane >> 2, tg = lane & 3;
    const int m0 = blockIdx.y * 64;
    const int n0 = blockIdx.x * 128;
    const int wm = (warp & 1) * 32;
    const int wn = (warp >> 1) * 32;

    const uint32_t sa = (uint32_t)__cvta_generic_to_shared(&As[0][0]);
    const uint32_t sb = (uint32_t)__cvta_generic_to_shared(&Bs[0][0]);

    float acc[2][4][4];
#pragma unroll
    for (int i = 0; i < 2; i++)
#pragma unroll
        for (int j = 0; j < 4; j++)
#pragma unroll
            for (int e = 0; e < 4; e++) acc[i][j][e] = 0.f;

    auto load_stage = [&](int kt, int s) {
        int ko = kt * 16;
        if (tid < 128) {
            int row = tid >> 1, seg = tid & 1;
            size_t src = (size_t)(m0 + row) * INPAD + ko + seg * 8;
            cpa16(sa + (uint32_t)(s * 64 * IGS + row * IGS + seg * 8) * 2, &d_Xh[src]);
        }
        {
            int row = tid >> 1, seg = tid & 1;
            size_t src = (size_t)(n0 + row) * INPAD + ko + seg * 8;
            cpa16(sb + (uint32_t)(s * 128 * IGS + row * IGS + seg * 8) * 2, &d_Wih[src]);
        }
    };

    load_stage(0, 0);
    cpa_commit();

    for (int kt = 0; kt < 19; kt++) {
        int s = kt & 1;
        if (kt < 18) { load_stage(kt + 1, s ^ 1); cpa_commit(); }
        if (kt < 18) cpa_wait1(); else cpa_wait0();
        __syncthreads();

        uint32_t a[2][4];
#pragma unroll
        for (int i = 0; i < 2; i++) {
            int r = wm + i * 16 + g;
            a[i][0] = *(const uint32_t*)&As[s][r * IGS + tg * 2];
            a[i][1] = *(const uint32_t*)&As[s][(r + 8) * IGS + tg * 2];
            a[i][2] = *(const uint32_t*)&As[s][r * IGS + tg * 2 + 8];
            a[i][3] = *(const uint32_t*)&As[s][(r + 8) * IGS + tg * 2 + 8];
        }
#pragma unroll
        for (int j = 0; j < 4; j++) {
            int n = wn + j * 8 + g;
            uint32_t b0 = *(const uint32_t*)&Bs[s][n * IGS + tg * 2];
            uint32_t b1 = *(const uint32_t*)&Bs[s][n * IGS + tg * 2 + 8];
#pragma unroll
            for (int i = 0; i < 2; i++) mma16816(acc[i][j], a[i], b0, b1);
        }
        __syncthreads();
    }

    // epilogue: add bias, scatter to IG[t][b][n] (m = b*1024 + t)
#pragma unroll
    for (int i = 0; i < 2; i++) {
#pragma unroll
        for (int j = 0; j < 4; j++) {
            int n = n0 + wn + j * 8 + tg * 2;
            float bb0 = bias[n], bb1 = bias[n + 1];
            int m = m0 + wm + i * 16 + g;
            {
                int tt = m & 1023, bi = m >> 10;
                *(float2*)&d_IG[((size_t)tt * BSZ + bi) * GDIM + n] =
                    make_float2(acc[i][j][0] + bb0, acc[i][j][1] + bb1);
            }
            {
                int m2 = m + 8;
                int tt = m2 & 1023, bi = m2 >> 10;
                *(float2*)&d_IG[((size_t)tt * BSZ + bi) * GDIM + n] =
                    make_float2(acc[i][j][2] + bb0, acc[i][j][3] + bb1);
            }
        }
    }
}

// ---------------- persistent GRU scan (plain fp16, 128 CTAs) ---------------
// 128 CTAs: mb = blockIdx.x&7 (32 batch rows), nb = blockIdx.x>>3 (32 h-cols).
// 8 warps: wm = warp&1 (16 rows), wn = warp>>1 (8 h-cols x 3 gates).
// W_hh tile (96x512 fp16) resident in smem; A (32x512) loaded once per step
// via cp.async.cg (L2 => coherent with other CTAs' stores); 2 syncs/step.
#define SCAN_CTAS 128
#define WST 520   // W smem row stride (halves)
#define AST 520   // A smem row stride (halves)
#define SCAN_SMEM ((96 * WST + 32 * AST) * 2)   // 133120 bytes

extern __shared__ __half smem_scan[];

__global__ void __launch_bounds__(256) scan_kernel(const float* __restrict__ b_n_p) {
    __half* W = smem_scan;                 // 96 x WST
    __half* A = W + 96 * WST;              // 32 x AST
    const uint32_t A_u32 = (uint32_t)__cvta_generic_to_shared(A);

    const int tid = threadIdx.x;
    const int warp = tid >> 5, lane = tid & 31;
    const int g = lane >> 2, tg = lane & 3;
    const int wm = warp & 1, wn = warp >> 1;
    const int mb = blockIdx.x & 7;
    const int nb = blockIdx.x >> 3;

    // Load resident W_hh tile: 96 rows (3 gates x 32 h-cols) x 512 k.
    for (int idx = tid; idx < 96 * 64; idx += 256) {
        int row = idx >> 6, seg = idx & 63;
        int gate = row >> 5, wi = row & 31;
        *(uint4*)&W[row * WST + seg * 8] =
            *(const uint4*)&d_Whh[(size_t)((gate << 9) + nb * 32 + wi) * HDIM + seg * 8];
    }
    __syncthreads();

    const int hc = nb * 32 + wn * 8 + tg * 2;
    float bn0 = b_n_p[hc], bn1 = b_n_p[hc + 1];

    float hreg[2][2];                      // [hh][cb]
#pragma unroll
    for (int hh = 0; hh < 2; hh++) { hreg[hh][0] = 0.f; hreg[hh][1] = 0.f; }

    // A-load mapping: 32 rows x 64 uint4; 8 threads/row, 8 uint4/thread
    const int a_row = tid >> 3, a_c8 = tid & 7;

    for (int t = 0; t < TLEN; t++) {
        const __half* hin = d_hh[t & 1];
        __half* hout = d_hh[(t + 1) & 1];

        // load full A tile for this step (L2 path)
        {
            const __half* src0 = hin + (size_t)(mb * 32 + a_row) * HDIM;
            uint32_t dst0 = A_u32 + (uint32_t)(a_row * AST) * 2;
#pragma unroll
            for (int j = 0; j < 8; j++) {
                int chunk = a_c8 + j * 8;          // uint4 index in row
                cpa16(dst0 + (uint32_t)(chunk * 8) * 2, src0 + chunk * 8);
            }
        }
        cpa_commit();
        cpa_wait0();
        __syncthreads();

        float acc[3][4];
#pragma unroll
        for (int gt = 0; gt < 3; gt++)
#pragma unroll
            for (int e = 0; e < 4; e++) acc[gt][e] = 0.f;

        const int r = wm * 16 + g;
#pragma unroll 4
        for (int ko = 0; ko < HDIM; ko += 16) {
            uint32_t a[4];
            a[0] = *(const uint32_t*)&A[r * AST + ko + tg * 2];
            a[1] = *(const uint32_t*)&A[(r + 8) * AST + ko + tg * 2];
            a[2] = *(const uint32_t*)&A[r * AST + ko + tg * 2 + 8];
            a[3] = *(const uint32_t*)&A[(r + 8) * AST + ko + tg * 2 + 8];
#pragma unroll
            for (int gate = 0; gate < 3; gate++) {
                int n = gate * 32 + wn * 8 + g;
                uint32_t b0 = *(const uint32_t*)&W[n * WST + ko + tg * 2];
                uint32_t b1 = *(const uint32_t*)&W[n * WST + ko + tg * 2 + 8];
                mma16816(acc[gate], a, b0, b1);
            }
        }

        // epilogue: gates (MUFU) + hidden update (h_old in regs)
#pragma unroll
        for (int hh = 0; hh < 2; hh++) {
            int bb = mb * 32 + wm * 16 + g + hh * 8;
            size_t ib = ((size_t)t * BSZ + bb) * GDIM + hc;
            float2 igr = *(const float2*)&d_IG[ib];
            float2 igz = *(const float2*)&d_IG[ib + 512];
            float2 ign = *(const float2*)&d_IG[ib + 1024];
            float hv[2];
#pragma unroll
            for (int cb = 0; cb < 2; cb++) {
                float ir  = cb ? igr.y : igr.x;
                float iz  = cb ? igz.y : igz.x;
                float inn = cb ? ign.y : ign.x;
                float bn  = cb ? bn1 : bn0;
                float rg = fast_sig(ir + acc[0][hh * 2 + cb]);
                float zg = fast_sig(iz + acc[1][hh * 2 + cb]);
                float ng = fast_tanh(inn + rg * (acc[2][hh * 2 + cb] + bn));
                float v = ng + zg * (hreg[hh][cb] - ng);
                hreg[hh][cb] = v;
                hv[cb] = v;
            }
            *(__half2*)&hout[bb * HDIM + hc] =
                __halves2half2(__float2half(hv[0]), __float2half(hv[1]));
            if (t == TLEN - 1)
                *(float2*)&d_hfinal[bb * HDIM + hc] = make_float2(hv[0], hv[1]);
        }

        // device-wide generation barrier (monotonic counter)
        if (t < TLEN - 1) {
            __threadfence();
            __syncthreads();
            if (tid == 0) {
                atomicAdd(&d_bar, 1u);
                unsigned tgt = (unsigned)SCAN_CTAS * (unsigned)(t + 1);
                volatile unsigned* p = &d_bar;
                while (*p < tgt) { }
                __threadfence();
            }
            __syncthreads();
        }
    }
}

// ---------------- tail: dropout (partitionable threefry) + LN + MLP --------
__global__ void __launch_bounds__(256) tail_kernel(
    const float* __restrict__ ln_w, const float* __restrict__ ln_b,
    const float* __restrict__ w1, const float* __restrict__ b1,
    const float* __restrict__ w2, const float* __restrict__ ob,
    float* __restrict__ out) {
    __shared__ float hs[512];
    __shared__ float r1[256], r2[256];
    const int bidx = blockIdx.x, tid = threadIdx.x;

    float s = 0.f, q = 0.f;
    for (int k = tid; k < 512; k += 256) {
        int i = bidx * 512 + k;
        uint2 o = threefry_0_42(0u, (uint32_t)i);
        uint32_t bits = o.x ^ o.y;
        float v = (bits >> 31) ? 0.f : d_hfinal[i] * 2.0f;
        hs[k] = v;
        s += v;
        q += v * v;
    }
    r1[tid] = s; r2[tid] = q;
    __syncthreads();
    for (int off = 128; off > 0; off >>= 1) {
        if (tid < off) { r1[tid] += r1[tid + off]; r2[tid] += r2[tid + off]; }
        __syncthreads();
    }
    float mu = r1[0] * (1.f / 512.f);
    float var = r2[0] * (1.f / 512.f) - mu * mu;
    float rstd = rsqrtf(var + 1e-5f);
    __syncthreads();
    for (int k = tid; k < 512; k += 256)
        hs[k] = (hs[k] - mu) * rstd * ln_w[k] + ln_b[k];
    __syncthreads();

    float a1 = b1[tid];
    const float* wrow = w1 + (size_t)tid * 512;
#pragma unroll 8
    for (int k = 0; k < 512; k++) a1 = fmaf(hs[k], wrow[k], a1);

    float p0 = a1 * w2[tid];
    float p1 = a1 * w2[256 + tid];
    __syncthreads();
    r1[tid] = p0; r2[tid] = p1;
    __syncthreads();
    for (int off = 128; off > 0; off >>= 1) {
        if (tid < off) { r1[tid] += r1[tid + off]; r2[tid] += r2[tid + off]; }
        __syncthreads();
    }
    if (tid == 0) {
        out[bidx * 2 + 0] = my_sig(r1[0] + ob[0]);
        out[bidx * 2 + 1] = my_sig(r2[0] + ob[1]);
    }
}

// ---------------- launcher --------------------------------------------------
extern "C" void kernel_launch(void* const* d_in, const int* in_sizes, int n_in,
                              void* d_out, int out_size) {
    const float* x     = (const float*)d_in[0];
    const float* w_ih  = (const float*)d_in[1];
    const float* w_hh  = (const float*)d_in[2];
    const float* b     = (const float*)d_in[3];
    const float* b_n   = (const float*)d_in[4];
    const float* ln_w  = (const float*)d_in[5];
    const float* ln_b  = (const float*)d_in[6];
    const float* w1    = (const float*)d_in[7];
    const float* b1    = (const float*)d_in[8];
    const float* w2    = (const float*)d_in[9];
    const float* ob    = (const float*)d_in[10];
    float* out = (float*)d_out;

    cudaFuncSetAttribute(scan_kernel, cudaFuncAttributeMaxDynamicSharedMemorySize, SCAN_SMEM);

    conv_x_kernel<<<BT / 8, 128>>>(x);
    conv_w_kernel<<<GDIM, 128>>>(w_ih, w_hh);
    init_kernel<<<64, 256>>>();
    gemm_ig_kernel<<<dim3(GDIM / 128, BT / 64), 256>>>(b);
    scan_kernel<<<SCAN_CTAS, 256, SCAN_SMEM>>>(b_n);
    tail_kernel<<<BSZ, 256>>>(ln_w, ln_b, w1, b1, w2, ob, out);
}

// round 17
// speedup vs baseline: 5.4017x; 1.3321x over previous
#include <cuda_runtime.h>
#include <cuda_fp16.h>
#include <cuda_bf16.h>
#include <cstdint>

// Problem sizes
#define BSZ   256
#define TLEN  1024
#define INDIM 302
#define INPAD 304            // padded K (mult of 16)
#define HDIM  512
#define GDIM  1536           // 3*H
#define BT    (BSZ*TLEN)     // 262144

// ---------------- device scratch (static; no cudaMalloc) -------------------
static __device__ __half   d_Xh[(size_t)BT * INPAD];
static __device__ __half   d_Wih[(size_t)GDIM * INPAD];
static __device__ __half   d_Whh[(size_t)GDIM * HDIM];
static __device__ float    d_IG[(size_t)TLEN * BSZ * GDIM];    // [T][B][3H]
static __device__ __half   d_hh[2][BSZ * HDIM];                // fp16 hidden, double buffer
static __device__ float    d_hfinal[BSZ * HDIM];
static __device__ unsigned d_bar;

// ---------------- cp.async helpers (cg = L2-only: cross-CTA coherent) ------
__device__ __forceinline__ void cpa16(uint32_t dst, const void* src) {
    asm volatile("cp.async.cg.shared.global [%0], [%1], 16;" :: "r"(dst), "l"(src));
}
__device__ __forceinline__ void cpa_commit() { asm volatile("cp.async.commit_group;"); }
__device__ __forceinline__ void cpa_wait0()  { asm volatile("cp.async.wait_group 0;"); }
__device__ __forceinline__ void cpa_wait1()  { asm volatile("cp.async.wait_group 1;"); }

// ---------------- ldmatrix helpers -----------------------------------------
__device__ __forceinline__ void ldsm_x4(uint32_t* r, uint32_t addr) {
    asm volatile("ldmatrix.sync.aligned.m8n8.x4.shared.b16 {%0,%1,%2,%3}, [%4];"
                 : "=r"(r[0]), "=r"(r[1]), "=r"(r[2]), "=r"(r[3]) : "r"(addr));
}
__device__ __forceinline__ void ldsm_x2(uint32_t& r0, uint32_t& r1, uint32_t addr) {
    asm volatile("ldmatrix.sync.aligned.m8n8.x2.shared.b16 {%0,%1}, [%2];"
                 : "=r"(r0), "=r"(r1) : "r"(addr));
}

// ---------------- fast MUFU gates (EX2/RCP, err ~1e-7 abs) ------------------
__device__ __forceinline__ float fast_sig(float x) {
    float e, r;
    asm("ex2.approx.ftz.f32 %0, %1;" : "=f"(e) : "f"(x * -1.4426950408889634f));
    asm("rcp.approx.ftz.f32 %0, %1;" : "=f"(r) : "f"(e + 1.0f));
    return r;
}
__device__ __forceinline__ float fast_tanh(float x) {
    float e, r;
    asm("ex2.approx.ftz.f32 %0, %1;" : "=f"(e) : "f"(x * 2.8853900817779268f));  // e^{2x}
    asm("rcp.approx.ftz.f32 %0, %1;" : "=f"(r) : "f"(e + 1.0f));
    return fmaf(-2.0f, r, 1.0f);
}

// ---------------- accurate exp/sig for the tail -----------------------------
__device__ __forceinline__ float my_exp(float x) {
    x = fminf(fmaxf(x, -87.0f), 87.0f);
    float n = rintf(x * 1.44269504088896341f);
    float r = fmaf(n, -0.693145751953125f, x);
    r = fmaf(n, -1.4286067653e-6f, r);
    float p = 1.9841269841e-4f;
    p = fmaf(p, r, 1.3888888889e-3f);
    p = fmaf(p, r, 8.3333333333e-3f);
    p = fmaf(p, r, 4.1666666667e-2f);
    p = fmaf(p, r, 1.6666666667e-1f);
    p = fmaf(p, r, 5.0e-1f);
    p = fmaf(p, r, 1.0f);
    p = fmaf(p, r, 1.0f);
    float s = __int_as_float(((int)n + 127) << 23);
    return p * s;
}
__device__ __forceinline__ float my_sig(float x) {
    return __fdiv_rn(1.0f, 1.0f + my_exp(-x));
}

// ---------------- mma.sync m16n8k16 fp16->fp32 -----------------------------
__device__ __forceinline__ void mma16816(float* c, const uint32_t* a, uint32_t b0, uint32_t b1) {
    asm volatile(
        "mma.sync.aligned.m16n8k16.row.col.f32.f16.f16.f32 "
        "{%0,%1,%2,%3}, {%4,%5,%6,%7}, {%8,%9}, {%0,%1,%2,%3};\n"
        : "+f"(c[0]), "+f"(c[1]), "+f"(c[2]), "+f"(c[3])
        : "r"(a[0]), "r"(a[1]), "r"(a[2]), "r"(a[3]), "r"(b0), "r"(b1));
}

// ---------------- threefry2x32 with key (0, 42) ----------------------------
__device__ __forceinline__ uint2 threefry_0_42(uint32_t x0, uint32_t x1) {
    const uint32_t k0 = 0u, k1 = 42u;
    const uint32_t k2 = k0 ^ k1 ^ 0x1BD11BDAu;
    const uint32_t ks[3] = {k0, k1, k2};
    const int rotA[4] = {13, 15, 26, 6};
    const int rotB[4] = {17, 29, 16, 24};
    x0 += ks[0]; x1 += ks[1];
#pragma unroll
    for (int i = 0; i < 5; i++) {
        const int* r = (i & 1) ? rotB : rotA;
#pragma unroll
        for (int j = 0; j < 4; j++) {
            x0 += x1;
            x1 = (x1 << r[j]) | (x1 >> (32 - r[j]));
            x1 ^= x0;
        }
        x0 += ks[(i + 1) % 3];
        x1 += ks[(i + 2) % 3] + (uint32_t)(i + 1);
    }
    return make_uint2(x0, x1);
}

// ---------------- conversion kernels ---------------------------------------
__global__ void conv_x_kernel(const float* __restrict__ x) {
    int m0 = blockIdx.x * 8;
#pragma unroll
    for (int r = 0; r < 8; r++) {
        int m = m0 + r;
        const float* src = x + (size_t)m * INDIM;
        __half* dh = d_Xh + (size_t)m * INPAD;
        for (int k = threadIdx.x; k < INPAD; k += blockDim.x)
            dh[k] = __float2half((k < INDIM) ? src[k] : 0.f);
    }
}

__global__ void conv_w_kernel(const float* __restrict__ wih, const float* __restrict__ whh) {
    int r = blockIdx.x;  // 0..1535
    for (int k = threadIdx.x; k < INPAD; k += blockDim.x)
        d_Wih[(size_t)r * INPAD + k] = __float2half((k < INDIM) ? wih[(size_t)r * INDIM + k] : 0.f);
    for (int k = threadIdx.x; k < HDIM; k += blockDim.x)
        d_Whh[(size_t)r * HDIM + k] = __float2half(whh[(size_t)r * HDIM + k]);
}

__global__ void init_kernel() {
    int idx = blockIdx.x * blockDim.x + threadIdx.x;
    if (idx == 0) d_bar = 0u;
    uint4 z = make_uint4(0u, 0u, 0u, 0u);
    int n = (BSZ * HDIM) / 8;
    uint4* p0 = (uint4*)d_hh[0];
    for (int i = idx; i < n; i += gridDim.x * blockDim.x) p0[i] = z;
}

// ---------------- IG GEMM (plain fp16, 2-stage cp.async) -------------------
// CTA tile 64(M) x 128(N), 8 warps (2x4), warp tile 32x32.
#define IGS 24  // smem row stride (halves), padded
__global__ void __launch_bounds__(256) gemm_ig_kernel(const float* __restrict__ bias) {
    __shared__ __half As[2][64 * IGS];
    __shared__ __half Bs[2][128 * IGS];
    const int tid = threadIdx.x;
    const int warp = tid >> 5, lane = tid & 31;
    const int g = lane >> 2, tg = lane & 3;
    const int m0 = blockIdx.y * 64;
    const int n0 = blockIdx.x * 128;
    const int wm = (warp & 1) * 32;
    const int wn = (warp >> 1) * 32;

    const uint32_t sa = (uint32_t)__cvta_generic_to_shared(&As[0][0]);
    const uint32_t sb = (uint32_t)__cvta_generic_to_shared(&Bs[0][0]);

    float acc[2][4][4];
#pragma unroll
    for (int i = 0; i < 2; i++)
#pragma unroll
        for (int j = 0; j < 4; j++)
#pragma unroll
            for (int e = 0; e < 4; e++) acc[i][j][e] = 0.f;

    auto load_stage = [&](int kt, int s) {
        int ko = kt * 16;
        if (tid < 128) {
            int row = tid >> 1, seg = tid & 1;
            size_t src = (size_t)(m0 + row) * INPAD + ko + seg * 8;
            cpa16(sa + (uint32_t)(s * 64 * IGS + row * IGS + seg * 8) * 2, &d_Xh[src]);
        }
        {
            int row = tid >> 1, seg = tid & 1;
            size_t src = (size_t)(n0 + row) * INPAD + ko + seg * 8;
            cpa16(sb + (uint32_t)(s * 128 * IGS + row * IGS + seg * 8) * 2, &d_Wih[src]);
        }
    };

    load_stage(0, 0);
    cpa_commit();

    for (int kt = 0; kt < 19; kt++) {
        int s = kt & 1;
        if (kt < 18) { load_stage(kt + 1, s ^ 1); cpa_commit(); }
        if (kt < 18) cpa_wait1(); else cpa_wait0();
        __syncthreads();

        uint32_t a[2][4];
#pragma unroll
        for (int i = 0; i < 2; i++) {
            int r = wm + i * 16 + g;
            a[i][0] = *(const uint32_t*)&As[s][r * IGS + tg * 2];
            a[i][1] = *(const uint32_t*)&As[s][(r + 8) * IGS + tg * 2];
            a[i][2] = *(const uint32_t*)&As[s][r * IGS + tg * 2 + 8];
            a[i][3] = *(const uint32_t*)&As[s][(r + 8) * IGS + tg * 2 + 8];
        }
#pragma unroll
        for (int j = 0; j < 4; j++) {
            int n = wn + j * 8 + g;
            uint32_t b0 = *(const uint32_t*)&Bs[s][n * IGS + tg * 2];
            uint32_t b1 = *(const uint32_t*)&Bs[s][n * IGS + tg * 2 + 8];
#pragma unroll
            for (int i = 0; i < 2; i++) mma16816(acc[i][j], a[i], b0, b1);
        }
        __syncthreads();
    }

    // epilogue: add bias, scatter to IG[t][b][n] (m = b*1024 + t)
#pragma unroll
    for (int i = 0; i < 2; i++) {
#pragma unroll
        for (int j = 0; j < 4; j++) {
            int n = n0 + wn + j * 8 + tg * 2;
            float bb0 = bias[n], bb1 = bias[n + 1];
            int m = m0 + wm + i * 16 + g;
            {
                int tt = m & 1023, bi = m >> 10;
                *(float2*)&d_IG[((size_t)tt * BSZ + bi) * GDIM + n] =
                    make_float2(acc[i][j][0] + bb0, acc[i][j][1] + bb1);
            }
            {
                int m2 = m + 8;
                int tt = m2 & 1023, bi = m2 >> 10;
                *(float2*)&d_IG[((size_t)tt * BSZ + bi) * GDIM + n] =
                    make_float2(acc[i][j][2] + bb0, acc[i][j][3] + bb1);
            }
        }
    }
}

// ---------------- persistent GRU scan (fp16, LDSM, IG-prefetch) ------------
// 128 CTAs: mb = blockIdx.x&7 (32 batch rows), nb = blockIdx.x>>3 (32 h-cols).
// 8 warps: wm = warp&1 (16 rows), wn = warp>>1 (8 h-cols x 3 gates).
// W_hh (96x512 fp16) smem-resident; A (32x512) one cp.async group per step;
// IG[t+1] prefetched to smem in its own group (hides DRAM latency off the
// critical path). Barrier: bar.sync + red.release.gpu / ld.acquire.gpu.
#define SCAN_CTAS 128
#define WST 520    // W smem row stride (halves)
#define AST 520    // A smem row stride (halves)
#define IGST 100   // IG smem row stride (floats)
#define SCAN_SMEM ((96 * WST + 32 * AST) * 2 + 2 * 32 * IGST * 4)  // 158720 B

extern __shared__ __half smem_scan[];

__global__ void __launch_bounds__(256) scan_kernel(const float* __restrict__ b_n_p) {
    __half* W = smem_scan;                 // 96 x WST
    __half* A = W + 96 * WST;              // 32 x AST
    float* IGs = (float*)(A + 32 * AST);   // 2 stages x 32 rows x IGST
    const uint32_t A_u32 = (uint32_t)__cvta_generic_to_shared(A);
    const uint32_t W_u32 = (uint32_t)__cvta_generic_to_shared(W);
    const uint32_t IG_u32 = (uint32_t)__cvta_generic_to_shared(IGs);

    const int tid = threadIdx.x;
    const int warp = tid >> 5, lane = tid & 31;
    const int g = lane >> 2, tg = lane & 3;
    const int wm = warp & 1, wn = warp >> 1;
    const int mb = blockIdx.x & 7;
    const int nb = blockIdx.x >> 3;

    // Load resident W_hh tile: 96 rows (3 gates x 32 h-cols) x 512 k.
    for (int idx = tid; idx < 96 * 64; idx += 256) {
        int row = idx >> 6, seg = idx & 63;
        int gate = row >> 5, wi = row & 31;
        *(uint4*)&W[row * WST + seg * 8] =
            *(const uint4*)&d_Whh[(size_t)((gate << 9) + nb * 32 + wi) * HDIM + seg * 8];
    }
    __syncthreads();

    const int hc = nb * 32 + wn * 8 + tg * 2;
    float bn0 = b_n_p[hc], bn1 = b_n_p[hc + 1];

    float hreg[2][2];
#pragma unroll
    for (int hh = 0; hh < 2; hh++) { hreg[hh][0] = 0.f; hreg[hh][1] = 0.f; }

    // A-load mapping: 32 rows x 64 uint4; 8 threads/row, 8 uint4/thread
    const int a_row = tid >> 3, a_c8 = tid & 7;

    // IG prefetch: 768 x 16B per stage; 3 per thread
    auto prefetch_ig = [&](int tt, int stage) {
#pragma unroll
        for (int j = 0; j < 3; j++) {
            int o = tid + j * 256;
            int row = o / 24, q = o % 24;
            int gate = q >> 3, c = (q & 7) * 4;
            const float* src =
                &d_IG[((size_t)tt * BSZ + mb * 32 + row) * GDIM + (gate << 9) + nb * 32 + c];
            cpa16(IG_u32 + (uint32_t)(((stage * 32 + row) * IGST + gate * 32 + c) * 4), src);
        }
    };

    // ldmatrix lane addresses (bytes): A x4 and per-gate W x2
    const uint32_t a_ldsm = A_u32 +
        (uint32_t)(((wm * 16 + (lane & 15)) * AST + (lane >> 4) * 8) * 2);
    uint32_t b_ldsm[3];
#pragma unroll
    for (int gate = 0; gate < 3; gate++)
        b_ldsm[gate] = W_u32 +
            (uint32_t)(((gate * 32 + wn * 8 + (lane & 7)) * WST + ((lane >> 3) & 1) * 8) * 2);

    // prologue: prefetch IG[0] into stage 0
    prefetch_ig(0, 0);
    cpa_commit();

    for (int t = 0; t < TLEN; t++) {
        const __half* hin = d_hh[t & 1];
        __half* hout = d_hh[(t + 1) & 1];

        // group: A tile for this step (L2 path)
        {
            const __half* src0 = hin + (size_t)(mb * 32 + a_row) * HDIM;
            uint32_t dst0 = A_u32 + (uint32_t)(a_row * AST) * 2;
#pragma unroll
            for (int j = 0; j < 8; j++) {
                int chunk = a_c8 + j * 8;
                cpa16(dst0 + (uint32_t)(chunk * 8) * 2, src0 + chunk * 8);
            }
        }
        cpa_commit();
        // group: IG for next step (DRAM; completes any time before next epilogue)
        int tn = (t + 1 < TLEN) ? t + 1 : t;
        prefetch_ig(tn, (t + 1) & 1);
        cpa_commit();

        cpa_wait1();            // A[t] (+ IG[t], long done); IG[t+1] in flight
        __syncthreads();

        float acc[3][4];
#pragma unroll
        for (int gt = 0; gt < 3; gt++)
#pragma unroll
            for (int e = 0; e < 4; e++) acc[gt][e] = 0.f;

#pragma unroll 4
        for (int ko = 0; ko < HDIM; ko += 16) {
            uint32_t a[4];
            ldsm_x4(a, a_ldsm + (uint32_t)(ko * 2));
#pragma unroll
            for (int gate = 0; gate < 3; gate++) {
                uint32_t b0, b1;
                ldsm_x2(b0, b1, b_ldsm[gate] + (uint32_t)(ko * 2));
                mma16816(acc[gate], a, b0, b1);
            }
        }

        // epilogue: gates (MUFU) + hidden update; IG from smem stage t&1
#pragma unroll
        for (int hh = 0; hh < 2; hh++) {
            int bb = mb * 32 + wm * 16 + g + hh * 8;
            const float* IGrow = IGs + ((size_t)((t & 1) * 32 + wm * 16 + g + hh * 8)) * IGST;
            int lc = wn * 8 + tg * 2;
            float2 igr = *(const float2*)&IGrow[lc];
            float2 igz = *(const float2*)&IGrow[32 + lc];
            float2 ign = *(const float2*)&IGrow[64 + lc];
            float hv[2];
#pragma unroll
            for (int cb = 0; cb < 2; cb++) {
                float ir  = cb ? igr.y : igr.x;
                float iz  = cb ? igz.y : igz.x;
                float inn = cb ? ign.y : ign.x;
                float bn  = cb ? bn1 : bn0;
                float rg = fast_sig(ir + acc[0][hh * 2 + cb]);
                float zg = fast_sig(iz + acc[1][hh * 2 + cb]);
                float ng = fast_tanh(inn + rg * (acc[2][hh * 2 + cb] + bn));
                float v = ng + zg * (hreg[hh][cb] - ng);
                hreg[hh][cb] = v;
                hv[cb] = v;
            }
            // store h via L2 (.cg) so cross-CTA readers + release fence agree
            uint32_t packed = (uint32_t)__half_as_ushort(__float2half(hv[0])) |
                              ((uint32_t)__half_as_ushort(__float2half(hv[1])) << 16);
            asm volatile("st.global.cg.u32 [%0], %1;"
                         :: "l"((uint32_t*)&hout[bb * HDIM + hc]), "r"(packed) : "memory");
            if (t == TLEN - 1)
                *(float2*)&d_hfinal[bb * HDIM + hc] = make_float2(hv[0], hv[1]);
        }

        // device-wide generation barrier: bar + release-add, acquire-poll
        if (t < TLEN - 1) {
            __syncthreads();
            if (tid == 0) {
                unsigned* bp = &d_bar;
                asm volatile("red.release.gpu.global.add.u32 [%0], %1;"
                             :: "l"(bp), "r"(1u) : "memory");
                unsigned tgt = (unsigned)SCAN_CTAS * (unsigned)(t + 1);
                unsigned v;
                do {
                    asm volatile("ld.acquire.gpu.global.u32 %0, [%1];"
                                 : "=r"(v) : "l"(bp) : "memory");
                } while (v < tgt);
            }
            __syncthreads();
        }
    }
}

// ---------------- tail: dropout (partitionable threefry) + LN + MLP --------
__global__ void __launch_bounds__(256) tail_kernel(
    const float* __restrict__ ln_w, const float* __restrict__ ln_b,
    const float* __restrict__ w1, const float* __restrict__ b1,
    const float* __restrict__ w2, const float* __restrict__ ob,
    float* __restrict__ out) {
    __shared__ float hs[512];
    __shared__ float r1[256], r2[256];
    const int bidx = blockIdx.x, tid = threadIdx.x;

    float s = 0.f, q = 0.f;
    for (int k = tid; k < 512; k += 256) {
        int i = bidx * 512 + k;
        uint2 o = threefry_0_42(0u, (uint32_t)i);
        uint32_t bits = o.x ^ o.y;
        float v = (bits >> 31) ? 0.f : d_hfinal[i] * 2.0f;
        hs[k] = v;
        s += v;
        q += v * v;
    }
    r1[tid] = s; r2[tid] = q;
    __syncthreads();
    for (int off = 128; off > 0; off >>= 1) {
        if (tid < off) { r1[tid] += r1[tid + off]; r2[tid] += r2[tid + off]; }
        __syncthreads();
    }
    float mu = r1[0] * (1.f / 512.f);
    float var = r2[0] * (1.f / 512.f) - mu * mu;
    float rstd = rsqrtf(var + 1e-5f);
    __syncthreads();
    for (int k = tid; k < 512; k += 256)
        hs[k] = (hs[k] - mu) * rstd * ln_w[k] + ln_b[k];
    __syncthreads();

    float a1 = b1[tid];
    const float* wrow = w1 + (size_t)tid * 512;
#pragma unroll 8
    for (int k = 0; k < 512; k++) a1 = fmaf(hs[k], wrow[k], a1);

    float p0 = a1 * w2[tid];
    float p1 = a1 * w2[256 + tid];
    __syncthreads();
    r1[tid] = p0; r2[tid] = p1;
    __syncthreads();
    for (int off = 128; off > 0; off >>= 1) {
        if (tid < off) { r1[tid] += r1[tid + off]; r2[tid] += r2[tid + off]; }
        __syncthreads();
    }
    if (tid == 0) {
        out[bidx * 2 + 0] = my_sig(r1[0] + ob[0]);
        out[bidx * 2 + 1] = my_sig(r2[0] + ob[1]);
    }
}

// ---------------- launcher --------------------------------------------------
extern "C" void kernel_launch(void* const* d_in, const int* in_sizes, int n_in,
                              void* d_out, int out_size) {
    const float* x     = (const float*)d_in[0];
    const float* w_ih  = (const float*)d_in[1];
    const float* w_hh  = (const float*)d_in[2];
    const float* b     = (const float*)d_in[3];
    const float* b_n   = (const float*)d_in[4];
    const float* ln_w  = (const float*)d_in[5];
    const float* ln_b  = (const float*)d_in[6];
    const float* w1    = (const float*)d_in[7];
    const float* b1    = (const float*)d_in[8];
    const float* w2    = (const float*)d_in[9];
    const float* ob    = (const float*)d_in[10];
    float* out = (float*)d_out;

    cudaFuncSetAttribute(scan_kernel, cudaFuncAttributeMaxDynamicSharedMemorySize, SCAN_SMEM);

    conv_x_kernel<<<BT / 8, 128>>>(x);
    conv_w_kernel<<<GDIM, 128>>>(w_ih, w_hh);
    init_kernel<<<64, 256>>>();
    gemm_ig_kernel<<<dim3(GDIM / 128, BT / 64), 256>>>(b);
    scan_kernel<<<SCAN_CTAS, 256, SCAN_SMEM>>>(b_n);
    tail_kernel<<<BSZ, 256>>>(ln_w, ln_b, w1, b1, w2, ob, out);
}